// round 10
// baseline (speedup 1.0000x reference)
#include <cuda_runtime.h>
#include <cuda_fp16.h>
#include <math.h>

#define S       64
#define LPREV   512
#define NF      193
#define NFRAMES 100
#define BATCH   64
#define NTH     512
#define NBT     (BATCH * NFRAMES)   // 6400

typedef unsigned long long u64;

// ---------------- scratch (static device allocations) ----------------
__device__ float  g_X [NBT * 256];
__device__ float  g_H1[NBT * 256];
__device__ float  g_H2[NBT * 256];
__device__ float  g_C [NBT * 512];
__device__ float  g_fwpre[NBT * 4 * 64];
__device__ int    g_period[NBT];
__device__ __half g_hWsd[128 * 320];

__device__ __forceinline__ float sigm(float x)   { return __fdividef(1.f, 1.f + __expf(-x)); }
__device__ __forceinline__ float tanh_f(float x) { return fmaf(2.f, __fdividef(1.f, 1.f + __expf(-2.f * x)), -1.f); }
__device__ __forceinline__ float red8(float v) {
    v += __shfl_xor_sync(0xffffffffu, v, 1);
    v += __shfl_xor_sync(0xffffffffu, v, 2);
    v += __shfl_xor_sync(0xffffffffu, v, 4);
    return v;
}

// ---- packed f32x2 helpers (FFMA2 — PTX-only on sm_103a) ----
__device__ __forceinline__ u64 pk2(float lo, float hi) {
    u64 r; asm("mov.b64 %0, {%1, %2};" : "=l"(r) : "f"(lo), "f"(hi)); return r;
}
__device__ __forceinline__ void fma2(u64& a, u64 w, u64 x) {
    asm("fma.rn.f32x2 %0, %1, %2, %0;" : "+l"(a) : "l"(w), "l"(x));
}
__device__ __forceinline__ float upk_sum(u64 a) {
    float lo, hi; asm("mov.b64 {%0, %1}, %2;" : "=f"(lo), "=f"(hi) : "l"(a));
    return lo + hi;
}
// 8 fp16 weights (uint4) x 8 fp32 activations (2 x ulonglong2), packed-FMA into acc
__device__ __forceinline__ void dot8h2(u64& acc, uint4 u, ulonglong2 xa, ulonglong2 xb) {
    float2 f0 = __half22float2(*reinterpret_cast<__half2*>(&u.x));
    float2 f1 = __half22float2(*reinterpret_cast<__half2*>(&u.y));
    float2 f2 = __half22float2(*reinterpret_cast<__half2*>(&u.z));
    float2 f3 = __half22float2(*reinterpret_cast<__half2*>(&u.w));
    fma2(acc, pk2(f0.x, f0.y), xa.x);
    fma2(acc, pk2(f1.x, f1.y), xa.y);
    fma2(acc, pk2(f2.x, f2.y), xb.x);
    fma2(acc, pk2(f3.x, f3.y), xb.y);
}
// pack 8 consecutive fp32 -> uint4 of 8 fp16
__device__ __forceinline__ uint4 pack8(const float* __restrict__ s) {
    union { uint4 u; __half2 h[4]; } r;
    r.h[0] = __floats2half2_rn(__ldg(&s[0]), __ldg(&s[1]));
    r.h[1] = __floats2half2_rn(__ldg(&s[2]), __ldg(&s[3]));
    r.h[2] = __floats2half2_rn(__ldg(&s[4]), __ldg(&s[5]));
    r.h[3] = __floats2half2_rn(__ldg(&s[6]), __ldg(&s[7]));
    return r.u;
}

// ---------------- prep kernels ----------------
__global__ void convert_wsd_kernel(const float* __restrict__ Wsd)
{
    int i = blockIdx.x * blockDim.x + threadIdx.x;
    if (i < 128 * 320) g_hWsd[i] = __float2half(Wsd[i]);
}

__global__ void build_x_kernel(const float* __restrict__ feats,
                               const float* __restrict__ glob)
{
    const int bt = blockIdx.x;
    const int b = bt / NFRAMES, t = bt % NFRAMES;
    const float* fb = feats + (long)b * NF * NFRAMES;
    for (int i = threadIdx.x; i < 192; i += blockDim.x)
        g_X[bt * 256 + i] = fb[i * NFRAMES + t];
    for (int i = threadIdx.x; i < 64; i += blockDim.x)
        g_X[bt * 256 + 192 + i] = glob[b * 64 + i];
    if (threadIdx.x == 0)
        g_period[bt] = (int)lrintf(fb[192 * NFRAMES + t]);
}

// C[M,N] = tanh(A[M,K] @ W[N,K]^T); tiles 64x64x64
__global__ __launch_bounds__(256)
void gemm_tanh_kernel(const float* __restrict__ Wt, int layer, int N, int K)
{
    const float* A = (layer == 0) ? g_X : (layer == 1) ? g_H1 : g_H2;
    float*       C = (layer == 0) ? g_H1 : (layer == 1) ? g_H2 : g_C;

    __shared__ float As[64][68];
    __shared__ float Ws[64][68];

    const int tid = threadIdx.x;
    const int m0 = blockIdx.y * 64, n0 = blockIdx.x * 64;
    const int lr = tid >> 2, lc = tid & 3;
    const int ty = tid >> 4, tx = tid & 15;

    float acc[4][4] = {};

    for (int k0 = 0; k0 < K; k0 += 64) {
        const float4* Arow = (const float4*)(A  + (long)(m0 + lr) * K + k0);
        const float4* Wrow = (const float4*)(Wt + (long)(n0 + lr) * K + k0);
        #pragma unroll
        for (int jj = 0; jj < 4; jj++) {
            float4 av = __ldg(&Arow[lc * 4 + jj]);
            float4 wv = __ldg(&Wrow[lc * 4 + jj]);
            int kk = lc * 16 + jj * 4;
            As[kk + 0][lr] = av.x; As[kk + 1][lr] = av.y;
            As[kk + 2][lr] = av.z; As[kk + 3][lr] = av.w;
            Ws[kk + 0][lr] = wv.x; Ws[kk + 1][lr] = wv.y;
            Ws[kk + 2][lr] = wv.z; Ws[kk + 3][lr] = wv.w;
        }
        __syncthreads();
        #pragma unroll
        for (int kk = 0; kk < 64; kk++) {
            float4 a = *(const float4*)&As[kk][ty * 4];
            float4 w = *(const float4*)&Ws[kk][tx * 4];
            acc[0][0] = fmaf(a.x, w.x, acc[0][0]); acc[0][1] = fmaf(a.x, w.y, acc[0][1]);
            acc[0][2] = fmaf(a.x, w.z, acc[0][2]); acc[0][3] = fmaf(a.x, w.w, acc[0][3]);
            acc[1][0] = fmaf(a.y, w.x, acc[1][0]); acc[1][1] = fmaf(a.y, w.y, acc[1][1]);
            acc[1][2] = fmaf(a.y, w.z, acc[1][2]); acc[1][3] = fmaf(a.y, w.w, acc[1][3]);
            acc[2][0] = fmaf(a.z, w.x, acc[2][0]); acc[2][1] = fmaf(a.z, w.y, acc[2][1]);
            acc[2][2] = fmaf(a.z, w.z, acc[2][2]); acc[2][3] = fmaf(a.z, w.w, acc[2][3]);
            acc[3][0] = fmaf(a.w, w.x, acc[3][0]); acc[3][1] = fmaf(a.w, w.y, acc[3][1]);
            acc[3][2] = fmaf(a.w, w.z, acc[3][2]); acc[3][3] = fmaf(a.w, w.w, acc[3][3]);
        }
        __syncthreads();
    }
    #pragma unroll
    for (int i = 0; i < 4; i++)
        #pragma unroll
        for (int j = 0; j < 4; j++)
            C[(long)(m0 + ty * 4 + i) * N + n0 + tx * 4 + j] = tanh_f(acc[i][j]);
}

// fwpre[bt][k][j] = Wfw[j,0:128] @ feat2s(bt,k) + Wfw[j,260:388] @ sfw(bt,k)
__global__ __launch_bounds__(256)
void fwpre_kernel(const float* __restrict__ Wfw)
{
    const int bt = blockIdx.x;
    const int t  = bt % NFRAMES;
    const int tid = threadIdx.x;
    __shared__ float sc[512], sp[512];
    for (int i = tid; i < 512; i += 256) {
        sc[i] = g_C[(long)bt * 512 + i];
        sp[i] = (t > 0) ? g_C[(long)(bt - 1) * 512 + i] : 0.f;
    }
    __syncthreads();
    const int p = tid & 3, row = tid >> 2;
    const float* wr = Wfw + row * 388;
    #pragma unroll
    for (int k = 0; k < 4; k++) {
        const float* sfw = (k == 0) ? sp : sc;
        const int ksf = (k == 0) ? 3 : (k - 1);
        float acc = 0.f;
        #pragma unroll 8
        for (int mm = 0; mm < 32; mm++) {
            int m = p * 32 + mm;
            acc = fmaf(__ldg(&wr[m]),       sc[4 * m + k],    acc);
            acc = fmaf(__ldg(&wr[260 + m]), sfw[4 * m + ksf], acc);
        }
        acc += __shfl_xor_sync(0xffffffffu, acc, 1);
        acc += __shfl_xor_sync(0xffffffffu, acc, 2);
        if (p == 0) g_fwpre[((long)bt * 4 + k) * 64 + row] = acc;
    }
}

// ---------------- serial recurrence ----------------

#define DYN_H16   (3 * 192 * 128 + 3 * 192 * 64)   // Wih x3 + Whh x3 = 110592 halfs
#define DYN_BYTES (DYN_H16 * 2)                    // 221184 B

__global__ __launch_bounds__(NTH, 1)
void fargan_kernel(const float* __restrict__ prev0,
                   const float* __restrict__ Wfw,     // (64,388)
                   const float* __restrict__ Wfw_g,   // (64,64)
                   const float* __restrict__ Wih1,    // (192,128)
                   const float* __restrict__ Whh1,    // (192,64)
                   const float* __restrict__ Wih2,
                   const float* __restrict__ Whh2,
                   const float* __restrict__ Wih3,
                   const float* __restrict__ Whh3,
                   const float* __restrict__ Wg1,     // (64,64)
                   const float* __restrict__ Wg2,
                   const float* __restrict__ Wg3,
                   const float* __restrict__ Wsg,     // (128,128)
                   const float* __restrict__ Wout,    // (64,128)
                   float* __restrict__ outp)          // (B, 25600)
{
    const int b   = blockIdx.x;
    const int tid = threadIdx.x;
    const int p   = tid & 7;        // 8 threads per row
    const int r0  = tid >> 3;       // 64 rows per pass

    extern __shared__ __half dynh[];
    __half* sWih = dynh;                 // 3 x 192 x 128
    __half* sWhh = dynh + 3 * 192 * 128; // 3 x 192 x 64

    __shared__ __align__(16) float ring[LPREV];
    __shared__ __align__(16) float st[2][3][S];      // double-buffered GRU states
    __shared__ __align__(16) float subin[136];       // [prev_sub(64) | lookback(68) | pad(4)]
    __shared__ __align__(16) float fwv[S];
    __shared__ __align__(16) float xcat[2 * S];
    __shared__ __align__(16) float skip[5 * S];      // [o1|o2|o3|fw|psub]
    __shared__ __align__(16) float sdv[2 * S];
    __shared__ __align__(16) float sov[2 * S];
    __shared__ __align__(16) float fwp4[256];
    __shared__ int period_sh;

    // ---- one-time: stage Wih / Whh as fp16 into smem ----
    {
        const float* src[3] = { Wih1, Wih2, Wih3 };
        #pragma unroll
        for (int m = 0; m < 3; m++)
            for (int i = tid; i < 192 * 128; i += NTH)
                sWih[m * 192 * 128 + i] = __float2half(__ldg(&src[m][i]));
        const float* srh[3] = { Whh1, Whh2, Whh3 };
        #pragma unroll
        for (int m = 0; m < 3; m++)
            for (int i = tid; i < 192 * 64; i += NTH)
                sWhh[m * 192 * 64 + i] = __float2half(__ldg(&srh[m][i]));
    }

    // ---- persistent register weight caches ----
    // Wfw2: cols [128,264) of Wfw, row r0, 17 consecutive floats per thread (fp32)
    float rfw2[17];
    #pragma unroll
    for (int i = 0; i < 17; i++) {
        int col = p * 17 + i;
        rfw2[i] = (col < 132) ? __ldg(&Wfw[r0 * 388 + 128 + col]) : 0.f;
    }
    // gates (Wg1,Wg2,Wg3,Wfwg): fp32 packed pairs, row r0, cols [8p, 8p+8)
    u64 rgate[4][4];
    {
        const float* gsrc[4] = { Wg1, Wg2, Wg3, Wfw_g };
        #pragma unroll
        for (int m = 0; m < 4; m++) {
            const float* w = gsrc[m] + r0 * 64 + 8 * p;
            #pragma unroll
            for (int j = 0; j < 4; j++)
                rgate[m][j] = pk2(__ldg(&w[2 * j]), __ldg(&w[2 * j + 1]));
        }
    }
    // Wsg: 128x128 fp16, rows r0 and r0+64, chunks p and p+8
    uint4 rsgh[2][2];
    #pragma unroll
    for (int it = 0; it < 2; it++) {
        rsgh[it][0] = pack8(Wsg + (r0 + 64 * it) * 128 + 8 * p);
        rsgh[it][1] = pack8(Wsg + (r0 + 64 * it) * 128 + 8 * (p + 8));
    }
    // Wout: 64x128 fp16, row r0, chunks p and p+8
    uint4 routh[2];
    routh[0] = pack8(Wout + r0 * 128 + 8 * p);
    routh[1] = pack8(Wout + r0 * 128 + 8 * (p + 8));

    // Wsd chunk pointers: per part m (0..4), thread covers rows r0 / r0+64, cols [64m+8p, +8)
    const uint4* wsd0 = (const uint4*)(g_hWsd + r0 * 320) + p;         // + 8*m
    const uint4* wsd1 = (const uint4*)(g_hWsd + (r0 + 64) * 320) + p;  // + 8*m

    // ---- init state ----
    for (int i = tid; i < LPREV; i += NTH) ring[i] = prev0[b * LPREV + i];
    if (tid < 3 * S) st[0][tid >> 6][tid & 63] = 0.f;
    if (tid >= 132 && tid < 136) subin[tid] = 0.f;
    int head = 0;
    int pb = 0;
    __syncthreads();

    for (int tf = 0; tf < NFRAMES; tf++) {
        const int bt = b * NFRAMES + tf;
        // ---- frame top: stage fwpre for all 4 subframes + period ----
        if (tid < 256) fwp4[tid] = __ldg(&g_fwpre[(long)bt * 256 + tid]);
        if (tid == 0) period_sh = __ldg(&g_period[bt]);
        __syncthreads();
        const int period = period_sh;

        for (int k = 0; k < 4; k++) {
            u64 sd0 = 0ull, sd1 = 0ull;   // incremental Wsd @ skip accumulators (f32x2)

            // ---- A: build [prev_sub | lookback], seed tails ----
            if (tid < 132) {
                if (tid < 64) {
                    float v = ring[(head + 448 + tid) & 511];
                    subin[tid] = v;
                    skip[256 + tid] = v;
                    xcat[64 + tid] = v;
                } else {
                    int i = tid - 64;
                    int idx = LPREV - period + i - 2;
                    if (idx >= LPREV) idx -= period;
                    subin[tid] = ring[(head + idx) & 511];
                }
            }
            __syncthreads();

            // ---- B: fwraw = tanh(Wfw2 @ subin + fwpre)  [+ Wsd psub part]
            float fwreg;
            {
                uint4 w0 = __ldg(wsd0 + 32), w1 = __ldg(wsd1 + 32);   // part m=4 (psub)
                float a = 0.f;
                #pragma unroll
                for (int i = 0; i < 17; i++)
                    a = fmaf(rfw2[i], subin[p * 17 + i], a);
                fwreg = tanh_f(red8(a) + fwp4[k * 64 + r0]);
                if (p == 0) fwv[r0] = fwreg;
                const ulonglong2* xs = (const ulonglong2*)(skip + 256);
                dot8h2(sd0, w0, xs[2 * p], xs[2 * p + 1]);
                dot8h2(sd1, w1, xs[2 * p], xs[2 * p + 1]);
            }
            __syncthreads();

            // ---- C: fw = fwraw * sigm(Wfwg @ fwv)   (fp32 packed gate)
            {
                const ulonglong2* x = (const ulonglong2*)fwv;
                ulonglong2 xa = x[2 * p], xb = x[2 * p + 1];
                u64 acc = 0ull;
                fma2(acc, rgate[3][0], xa.x); fma2(acc, rgate[3][1], xa.y);
                fma2(acc, rgate[3][2], xb.x); fma2(acc, rgate[3][3], xb.y);
                fwreg = fwreg * sigm(red8(upk_sum(acc)));
                if (p == 0) { skip[192 + r0] = fwreg; xcat[r0] = fwreg; }
            }
            __syncthreads();

            // ---- 3 x (GRU fused + GLU fused), weights in smem fp16 ----
            #pragma unroll
            for (int L = 0; L < 3; L++) {
                const __half* WI = sWih + L * 192 * 128;
                const __half* WH = sWhh + L * 192 * 64;
                const float* sto = st[pb][L];
                float* stn = st[pb ^ 1][L];
                float streg;
                {
                    // Wsd part for this stage: L=0 -> fw (m=3), L=1 -> o1 (m=0), L=2 -> o2 (m=1)
                    const int m = (L == 0) ? 3 : (L - 1);
                    uint4 w0 = __ldg(wsd0 + 8 * m), w1 = __ldg(wsd1 + 8 * m);

                    const ulonglong2* x = (const ulonglong2*)xcat;
                    ulonglong2 xa0 = x[2 * p], xa1 = x[2 * p + 1];
                    ulonglong2 xb0 = x[2 * p + 16], xb1 = x[2 * p + 17];
                    const ulonglong2* sx = (const ulonglong2*)sto;
                    ulonglong2 sv0 = sx[2 * p], sv1 = sx[2 * p + 1];
                    float gi[3], gh[3];
                    #pragma unroll
                    for (int it = 0; it < 3; it++) {
                        const uint4* wi = (const uint4*)(WI + (r0 + (it << 6)) * 128);
                        u64 ai = 0ull;
                        dot8h2(ai, wi[p], xa0, xa1);
                        dot8h2(ai, wi[p + 8], xb0, xb1);
                        gi[it] = red8(upk_sum(ai));
                        const uint4* wh = (const uint4*)(WH + (r0 + (it << 6)) * 64);
                        u64 ah = 0ull;
                        dot8h2(ah, wh[p], sv0, sv1);
                        gh[it] = red8(upk_sum(ah));
                    }
                    float r = sigm(gi[0] + gh[0]);
                    float z = sigm(gi[1] + gh[1]);
                    float n = tanh_f(gi[2] + r * gh[2]);
                    streg = (1.f - z) * n + z * sto[r0];
                    if (p == 0) stn[r0] = streg;

                    const ulonglong2* xm = (const ulonglong2*)(skip + 64 * m);
                    dot8h2(sd0, w0, xm[2 * p], xm[2 * p + 1]);
                    dot8h2(sd1, w1, xm[2 * p], xm[2 * p + 1]);
                }
                __syncthreads();
                {
                    const ulonglong2* x = (const ulonglong2*)stn;
                    ulonglong2 xa = x[2 * p], xb = x[2 * p + 1];
                    u64 acc = 0ull;
                    fma2(acc, rgate[L][0], xa.x); fma2(acc, rgate[L][1], xa.y);
                    fma2(acc, rgate[L][2], xb.x); fma2(acc, rgate[L][3], xb.y);
                    float v = streg * sigm(red8(upk_sum(acc)));
                    if (p == 0) {
                        skip[64 * L + r0] = v;
                        if (L < 2) xcat[r0] = v;
                    }
                }
                __syncthreads();
            }

            // ---- J (mini): add o3 part, finalize sdv ----
            float sdva[2];
            {
                uint4 w0 = __ldg(wsd0 + 16), w1 = __ldg(wsd1 + 16);   // part m=2 (o3)
                const ulonglong2* xm = (const ulonglong2*)(skip + 128);
                dot8h2(sd0, w0, xm[2 * p], xm[2 * p + 1]);
                dot8h2(sd1, w1, xm[2 * p], xm[2 * p + 1]);
                sdva[0] = tanh_f(red8(upk_sum(sd0)));
                sdva[1] = tanh_f(red8(upk_sum(sd1)));
                if (p == 0) { sdv[r0] = sdva[0]; sdv[64 + r0] = sdva[1]; }
            }
            __syncthreads();

            // ---- K: sov = sdv * sigm(Wsg @ sdv)   (register fp16)
            {
                const ulonglong2* x = (const ulonglong2*)sdv;
                ulonglong2 xa0 = x[2 * p], xa1 = x[2 * p + 1];
                ulonglong2 xb0 = x[2 * p + 16], xb1 = x[2 * p + 17];
                #pragma unroll
                for (int it = 0; it < 2; it++) {
                    u64 acc = 0ull;
                    dot8h2(acc, rsgh[it][0], xa0, xa1);
                    dot8h2(acc, rsgh[it][1], xb0, xb1);
                    float a = red8(upk_sum(acc));
                    if (p == 0) sov[r0 + 64 * it] = sdva[it] * sigm(a);
                }
            }
            __syncthreads();

            // ---- L: out = tanh(Wout @ sov); emit + ring update   (register fp16)
            {
                const ulonglong2* x = (const ulonglong2*)sov;
                u64 acc = 0ull;
                dot8h2(acc, routh[0], x[2 * p], x[2 * p + 1]);
                dot8h2(acc, routh[1], x[2 * p + 16], x[2 * p + 17]);
                float out = tanh_f(red8(upk_sum(acc)));
                if (p == 0) {
                    outp[(long)b * (NFRAMES * 4 * S) + tf * (4 * S) + k * S + r0] = out;
                    ring[(head + r0) & 511] = out;
                }
            }
            head = (head + 64) & 511;
            pb ^= 1;
            __syncthreads();
        }
    }
}

extern "C" void kernel_launch(void* const* d_in, const int* in_sizes, int n_in,
                              void* d_out, int out_size)
{
    const float* feats = (const float*)d_in[0];
    const float* glob  = (const float*)d_in[1];
    const float* prev0 = (const float*)d_in[2];
    const float* Wc1   = (const float*)d_in[3];
    const float* Wc2   = (const float*)d_in[4];
    const float* Wc3   = (const float*)d_in[5];
    const float* Wfw   = (const float*)d_in[6];
    const float* Wfw_g = (const float*)d_in[7];
    const float* Wih1  = (const float*)d_in[8];
    const float* Whh1  = (const float*)d_in[9];
    const float* Wih2  = (const float*)d_in[10];
    const float* Whh2  = (const float*)d_in[11];
    const float* Wih3  = (const float*)d_in[12];
    const float* Whh3  = (const float*)d_in[13];
    const float* Wg1   = (const float*)d_in[14];
    const float* Wg2   = (const float*)d_in[15];
    const float* Wg3   = (const float*)d_in[16];
    const float* Wsg   = (const float*)d_in[17];
    const float* Wsd   = (const float*)d_in[18];
    const float* Wout  = (const float*)d_in[19];
    float* outp = (float*)d_out;

    static bool attr_set = false;
    if (!attr_set) {
        cudaFuncSetAttribute(fargan_kernel,
                             cudaFuncAttributeMaxDynamicSharedMemorySize, DYN_BYTES);
        attr_set = true;
    }

    convert_wsd_kernel<<<(128 * 320 + 255) / 256, 256>>>(Wsd);
    build_x_kernel<<<NBT, 64>>>(feats, glob);
    gemm_tanh_kernel<<<dim3(4, 100), 256>>>(Wc1, 0, 256, 256);
    gemm_tanh_kernel<<<dim3(4, 100), 256>>>(Wc2, 1, 256, 256);
    gemm_tanh_kernel<<<dim3(8, 100), 256>>>(Wc3, 2, 512, 256);
    fwpre_kernel<<<NBT, 256>>>(Wfw);
    fargan_kernel<<<BATCH, NTH, DYN_BYTES>>>(prev0,
                                  Wfw, Wfw_g,
                                  Wih1, Whh1, Wih2, Whh2, Wih3, Whh3,
                                  Wg1, Wg2, Wg3, Wsg, Wout, outp);
}

// round 11
// speedup vs baseline: 1.4285x; 1.4285x over previous
#include <cuda_runtime.h>
#include <cuda_fp16.h>
#include <math.h>

#define S       64
#define LPREV   512
#define NF      193
#define NFRAMES 100
#define BATCH   64
#define NTH     512
#define NBT     (BATCH * NFRAMES)   // 6400

// ---------------- scratch (static device allocations) ----------------
__device__ float  g_X [NBT * 256];
__device__ float  g_H1[NBT * 256];
__device__ float  g_H2[NBT * 256];
__device__ float  g_C [NBT * 512];
__device__ float  g_fwpre[NBT * 4 * 64];
__device__ int    g_period[NBT];

__device__ __forceinline__ float sigm(float x)   { return __fdividef(1.f, 1.f + __expf(-x)); }
__device__ __forceinline__ float tanh_f(float x) { return fmaf(2.f, __fdividef(1.f, 1.f + __expf(-2.f * x)), -1.f); }
__device__ __forceinline__ float red8(float v) {
    v += __shfl_xor_sync(0xffffffffu, v, 1);
    v += __shfl_xor_sync(0xffffffffu, v, 2);
    v += __shfl_xor_sync(0xffffffffu, v, 4);
    return v;
}
// dot of 8 fp16 weights (one uint4) with 8 fp32 inputs (two float4)
__device__ __forceinline__ float dot8h(uint4 u, float4 xa, float4 xb) {
    float2 f0 = __half22float2(*reinterpret_cast<__half2*>(&u.x));
    float2 f1 = __half22float2(*reinterpret_cast<__half2*>(&u.y));
    float2 f2 = __half22float2(*reinterpret_cast<__half2*>(&u.z));
    float2 f3 = __half22float2(*reinterpret_cast<__half2*>(&u.w));
    float a = fmaf(f0.x, xa.x, f0.y * xa.y);
    a = fmaf(f1.x, xa.z, a); a = fmaf(f1.y, xa.w, a);
    a = fmaf(f2.x, xb.x, a); a = fmaf(f2.y, xb.y, a);
    a = fmaf(f3.x, xb.z, a); a = fmaf(f3.y, xb.w, a);
    return a;
}
// dot of 8 fp32 weights (two float4) with 8 fp32 inputs (two float4)
__device__ __forceinline__ float dot8f(float4 wa, float4 wb, float4 xa, float4 xb) {
    float a = wa.x * xa.x;
    a = fmaf(wa.y, xa.y, a);
    a = fmaf(wa.z, xa.z, a); a = fmaf(wa.w, xa.w, a);
    a = fmaf(wb.x, xb.x, a); a = fmaf(wb.y, xb.y, a);
    a = fmaf(wb.z, xb.z, a); a = fmaf(wb.w, xb.w, a);
    return a;
}
// pack 8 consecutive fp32 -> uint4 of 8 fp16
__device__ __forceinline__ uint4 pack8(const float* __restrict__ s) {
    union { uint4 u; __half2 h[4]; } r;
    r.h[0] = __floats2half2_rn(__ldg(&s[0]), __ldg(&s[1]));
    r.h[1] = __floats2half2_rn(__ldg(&s[2]), __ldg(&s[3]));
    r.h[2] = __floats2half2_rn(__ldg(&s[4]), __ldg(&s[5]));
    r.h[3] = __floats2half2_rn(__ldg(&s[6]), __ldg(&s[7]));
    return r.u;
}

// ---------------- prep kernels ----------------
__global__ void build_x_kernel(const float* __restrict__ feats,
                               const float* __restrict__ glob)
{
    const int bt = blockIdx.x;
    const int b = bt / NFRAMES, t = bt % NFRAMES;
    const float* fb = feats + (long)b * NF * NFRAMES;
    for (int i = threadIdx.x; i < 192; i += blockDim.x)
        g_X[bt * 256 + i] = fb[i * NFRAMES + t];
    for (int i = threadIdx.x; i < 64; i += blockDim.x)
        g_X[bt * 256 + 192 + i] = glob[b * 64 + i];
    if (threadIdx.x == 0)
        g_period[bt] = (int)lrintf(fb[192 * NFRAMES + t]);
}

// C[M,N] = tanh(A[M,K] @ W[N,K]^T); tiles 64x64x64
__global__ __launch_bounds__(256)
void gemm_tanh_kernel(const float* __restrict__ Wt, int layer, int N, int K)
{
    const float* A = (layer == 0) ? g_X : (layer == 1) ? g_H1 : g_H2;
    float*       C = (layer == 0) ? g_H1 : (layer == 1) ? g_H2 : g_C;

    __shared__ float As[64][68];
    __shared__ float Ws[64][68];

    const int tid = threadIdx.x;
    const int m0 = blockIdx.y * 64, n0 = blockIdx.x * 64;
    const int lr = tid >> 2, lc = tid & 3;
    const int ty = tid >> 4, tx = tid & 15;

    float acc[4][4] = {};

    for (int k0 = 0; k0 < K; k0 += 64) {
        const float4* Arow = (const float4*)(A  + (long)(m0 + lr) * K + k0);
        const float4* Wrow = (const float4*)(Wt + (long)(n0 + lr) * K + k0);
        #pragma unroll
        for (int jj = 0; jj < 4; jj++) {
            float4 av = __ldg(&Arow[lc * 4 + jj]);
            float4 wv = __ldg(&Wrow[lc * 4 + jj]);
            int kk = lc * 16 + jj * 4;
            As[kk + 0][lr] = av.x; As[kk + 1][lr] = av.y;
            As[kk + 2][lr] = av.z; As[kk + 3][lr] = av.w;
            Ws[kk + 0][lr] = wv.x; Ws[kk + 1][lr] = wv.y;
            Ws[kk + 2][lr] = wv.z; Ws[kk + 3][lr] = wv.w;
        }
        __syncthreads();
        #pragma unroll
        for (int kk = 0; kk < 64; kk++) {
            float4 a = *(const float4*)&As[kk][ty * 4];
            float4 w = *(const float4*)&Ws[kk][tx * 4];
            acc[0][0] = fmaf(a.x, w.x, acc[0][0]); acc[0][1] = fmaf(a.x, w.y, acc[0][1]);
            acc[0][2] = fmaf(a.x, w.z, acc[0][2]); acc[0][3] = fmaf(a.x, w.w, acc[0][3]);
            acc[1][0] = fmaf(a.y, w.x, acc[1][0]); acc[1][1] = fmaf(a.y, w.y, acc[1][1]);
            acc[1][2] = fmaf(a.y, w.z, acc[1][2]); acc[1][3] = fmaf(a.y, w.w, acc[1][3]);
            acc[2][0] = fmaf(a.z, w.x, acc[2][0]); acc[2][1] = fmaf(a.z, w.y, acc[2][1]);
            acc[2][2] = fmaf(a.z, w.z, acc[2][2]); acc[2][3] = fmaf(a.z, w.w, acc[2][3]);
            acc[3][0] = fmaf(a.w, w.x, acc[3][0]); acc[3][1] = fmaf(a.w, w.y, acc[3][1]);
            acc[3][2] = fmaf(a.w, w.z, acc[3][2]); acc[3][3] = fmaf(a.w, w.w, acc[3][3]);
        }
        __syncthreads();
    }
    #pragma unroll
    for (int i = 0; i < 4; i++)
        #pragma unroll
        for (int j = 0; j < 4; j++)
            C[(long)(m0 + ty * 4 + i) * N + n0 + tx * 4 + j] = tanh_f(acc[i][j]);
}

// fwpre[bt][k][j] = Wfw[j,0:128] @ feat2s(bt,k) + Wfw[j,260:388] @ sfw(bt,k)
__global__ __launch_bounds__(256)
void fwpre_kernel(const float* __restrict__ Wfw)
{
    const int bt = blockIdx.x;
    const int t  = bt % NFRAMES;
    const int tid = threadIdx.x;
    __shared__ float sc[512], sp[512];
    for (int i = tid; i < 512; i += 256) {
        sc[i] = g_C[(long)bt * 512 + i];
        sp[i] = (t > 0) ? g_C[(long)(bt - 1) * 512 + i] : 0.f;
    }
    __syncthreads();
    const int p = tid & 3, row = tid >> 2;
    const float* wr = Wfw + row * 388;
    #pragma unroll
    for (int k = 0; k < 4; k++) {
        const float* sfw = (k == 0) ? sp : sc;
        const int ksf = (k == 0) ? 3 : (k - 1);
        float acc = 0.f;
        #pragma unroll 8
        for (int mm = 0; mm < 32; mm++) {
            int m = p * 32 + mm;
            acc = fmaf(__ldg(&wr[m]),       sc[4 * m + k],    acc);
            acc = fmaf(__ldg(&wr[260 + m]), sfw[4 * m + ksf], acc);
        }
        acc += __shfl_xor_sync(0xffffffffu, acc, 1);
        acc += __shfl_xor_sync(0xffffffffu, acc, 2);
        if (p == 0) g_fwpre[((long)bt * 4 + k) * 64 + row] = acc;
    }
}

// ---------------- serial recurrence ----------------

#define DYN_H16   (3 * 192 * 128 + 3 * 192 * 64)   // Wih x3 + Whh x3 = 110592 halfs
#define DYN_BYTES (DYN_H16 * 2)                    // 221184 B

__global__ __launch_bounds__(NTH, 1)
void fargan_kernel(const float* __restrict__ prev0,
                   const float* __restrict__ Wfw,     // (64,388)
                   const float* __restrict__ Wfw_g,   // (64,64)
                   const float* __restrict__ Wih1,    // (192,128)
                   const float* __restrict__ Whh1,    // (192,64)
                   const float* __restrict__ Wih2,
                   const float* __restrict__ Whh2,
                   const float* __restrict__ Wih3,
                   const float* __restrict__ Whh3,
                   const float* __restrict__ Wg1,     // (64,64)
                   const float* __restrict__ Wg2,
                   const float* __restrict__ Wg3,
                   const float* __restrict__ Wsg,     // (128,128)
                   const float* __restrict__ Wsd,     // (128,320)
                   const float* __restrict__ Wout,    // (64,128)
                   float* __restrict__ outp)          // (B, 25600)
{
    const int b   = blockIdx.x;
    const int tid = threadIdx.x;
    const int p   = tid & 7;        // 8 threads per row
    const int r0  = tid >> 3;       // 64 rows per pass

    extern __shared__ __half dynh[];
    __half* sWih = dynh;                 // 3 x 192 x 128
    __half* sWhh = dynh + 3 * 192 * 128; // 3 x 192 x 64

    __shared__ __align__(16) float ring[LPREV];
    __shared__ __align__(16) float st[2][3][S];      // double-buffered GRU states
    __shared__ __align__(16) float subin[136];       // [prev_sub(64) | lookback(68) | pad(4)]
    __shared__ __align__(16) float fwv[S];
    __shared__ __align__(16) float xcat[2 * S];
    __shared__ __align__(16) float skip[5 * S];      // [o1|o2|o3|fw|psub]
    __shared__ __align__(16) float sdv[2 * S];
    __shared__ __align__(16) float sov[2 * S];
    __shared__ __align__(16) float fwp4[256];
    __shared__ int period_sh;

    // ---- one-time: stage Wih / Whh as fp16 into smem ----
    {
        const float* src[3] = { Wih1, Wih2, Wih3 };
        #pragma unroll
        for (int m = 0; m < 3; m++)
            for (int i = tid; i < 192 * 128; i += NTH)
                sWih[m * 192 * 128 + i] = __float2half(__ldg(&src[m][i]));
        const float* srh[3] = { Whh1, Whh2, Whh3 };
        #pragma unroll
        for (int m = 0; m < 3; m++)
            for (int i = tid; i < 192 * 64; i += NTH)
                sWhh[m * 192 * 64 + i] = __float2half(__ldg(&srh[m][i]));
    }

    // ---- persistent register weight caches ----
    // Wfw2: cols [128,264) of Wfw, row r0, 17 consecutive floats per thread (fp32)
    float rfw2[17];
    #pragma unroll
    for (int i = 0; i < 17; i++) {
        int col = p * 17 + i;
        rfw2[i] = (col < 132) ? __ldg(&Wfw[r0 * 388 + 128 + col]) : 0.f;
    }
    // gates (Wg1,Wg2,Wg3,Wfwg): fp32, row r0, cols [8p, 8p+8)  (32 regs)
    float4 rgf[4][2];
    {
        const float* gsrc[4] = { Wg1, Wg2, Wg3, Wfw_g };
        #pragma unroll
        for (int m = 0; m < 4; m++) {
            const float4* w = (const float4*)(gsrc[m] + r0 * 64 + 8 * p);
            rgf[m][0] = __ldg(&w[0]);
            rgf[m][1] = __ldg(&w[1]);
        }
    }
    // Wsg: 128x128 fp16, rows r0 and r0+64, chunks p and p+8
    uint4 rsgh[2][2];
    #pragma unroll
    for (int it = 0; it < 2; it++) {
        rsgh[it][0] = pack8(Wsg + (r0 + 64 * it) * 128 + 8 * p);
        rsgh[it][1] = pack8(Wsg + (r0 + 64 * it) * 128 + 8 * (p + 8));
    }
    // Wout: 64x128 fp16, row r0, chunks p and p+8
    uint4 routh[2];
    routh[0] = pack8(Wout + r0 * 128 + 8 * p);
    routh[1] = pack8(Wout + r0 * 128 + 8 * (p + 8));

    // Wsd fp32 row pointers: part m (0..4), thread covers rows r0 / r0+64, cols [64m+8p, +8)
    const float4* wsdf0 = (const float4*)(Wsd + r0 * 320);         // float4 idx: 16m + 2p
    const float4* wsdf1 = (const float4*)(Wsd + (r0 + 64) * 320);

    // ---- init state ----
    for (int i = tid; i < LPREV; i += NTH) ring[i] = prev0[b * LPREV + i];
    if (tid < 3 * S) st[0][tid >> 6][tid & 63] = 0.f;
    if (tid >= 132 && tid < 136) subin[tid] = 0.f;
    int head = 0;
    int pb = 0;
    __syncthreads();

    for (int tf = 0; tf < NFRAMES; tf++) {
        const int bt = b * NFRAMES + tf;
        // ---- frame top: stage fwpre for all 4 subframes + period ----
        if (tid < 256) fwp4[tid] = __ldg(&g_fwpre[(long)bt * 256 + tid]);
        if (tid == 0) period_sh = __ldg(&g_period[bt]);
        __syncthreads();
        const int period = period_sh;

        for (int k = 0; k < 4; k++) {
            float sd0 = 0.f, sd1 = 0.f;   // incremental Wsd @ skip accumulators

            // ---- A: build [prev_sub | lookback], seed tails ----
            if (tid < 132) {
                if (tid < 64) {
                    float v = ring[(head + 448 + tid) & 511];
                    subin[tid] = v;
                    skip[256 + tid] = v;
                    xcat[64 + tid] = v;
                } else {
                    int i = tid - 64;
                    int idx = LPREV - period + i - 2;
                    if (idx >= LPREV) idx -= period;
                    subin[tid] = ring[(head + idx) & 511];
                }
            }
            __syncthreads();

            // ---- B: fwraw = tanh(Wfw2 @ subin + fwpre)  [+ Wsd psub part, fp32]
            float fwreg;
            {
                float4 wa0 = __ldg(&wsdf0[64 + 2 * p]), wb0 = __ldg(&wsdf0[64 + 2 * p + 1]);
                float4 wa1 = __ldg(&wsdf1[64 + 2 * p]), wb1 = __ldg(&wsdf1[64 + 2 * p + 1]);
                float a = 0.f;
                #pragma unroll
                for (int i = 0; i < 17; i++)
                    a = fmaf(rfw2[i], subin[p * 17 + i], a);
                fwreg = tanh_f(red8(a) + fwp4[k * 64 + r0]);
                if (p == 0) fwv[r0] = fwreg;
                const float4* xs = (const float4*)(skip + 256);
                float4 xa = xs[2 * p], xb = xs[2 * p + 1];
                sd0 += dot8f(wa0, wb0, xa, xb);
                sd1 += dot8f(wa1, wb1, xa, xb);
            }
            __syncthreads();

            // ---- C: fw = fwraw * sigm(Wfwg @ fwv)   (fp32 register gate)
            {
                const float4* x = (const float4*)fwv;
                float acc = red8(dot8f(rgf[3][0], rgf[3][1], x[2 * p], x[2 * p + 1]));
                fwreg = fwreg * sigm(acc);
                if (p == 0) { skip[192 + r0] = fwreg; xcat[r0] = fwreg; }
            }
            __syncthreads();

            // ---- 3 x (GRU fused + GLU fused), weights in smem fp16 ----
            #pragma unroll
            for (int L = 0; L < 3; L++) {
                const __half* WI = sWih + L * 192 * 128;
                const __half* WH = sWhh + L * 192 * 64;
                const float* sto = st[pb][L];
                float* stn = st[pb ^ 1][L];
                float streg;
                {
                    // Wsd part for this stage: L=0 -> fw (m=3), L=1 -> o1 (m=0), L=2 -> o2 (m=1)
                    const int m = (L == 0) ? 3 : (L - 1);
                    float4 wa0 = __ldg(&wsdf0[16 * m + 2 * p]), wb0 = __ldg(&wsdf0[16 * m + 2 * p + 1]);
                    float4 wa1 = __ldg(&wsdf1[16 * m + 2 * p]), wb1 = __ldg(&wsdf1[16 * m + 2 * p + 1]);

                    const float4* x = (const float4*)xcat;
                    float4 xa0 = x[2 * p], xa1 = x[2 * p + 1];
                    float4 xb0 = x[2 * p + 16], xb1 = x[2 * p + 17];
                    float4 sv0 = ((const float4*)sto)[2 * p], sv1 = ((const float4*)sto)[2 * p + 1];
                    float gi[3], gh[3];
                    #pragma unroll
                    for (int it = 0; it < 3; it++) {
                        const uint4* wi = (const uint4*)(WI + (r0 + (it << 6)) * 128);
                        float a = dot8h(wi[p], xa0, xa1) + dot8h(wi[p + 8], xb0, xb1);
                        gi[it] = red8(a);
                        const uint4* wh = (const uint4*)(WH + (r0 + (it << 6)) * 64);
                        gh[it] = red8(dot8h(wh[p], sv0, sv1));
                    }
                    float r = sigm(gi[0] + gh[0]);
                    float z = sigm(gi[1] + gh[1]);
                    float n = tanh_f(gi[2] + r * gh[2]);
                    streg = (1.f - z) * n + z * sto[r0];
                    if (p == 0) stn[r0] = streg;

                    const float4* xm = (const float4*)(skip + 64 * m);
                    float4 xa = xm[2 * p], xb = xm[2 * p + 1];
                    sd0 += dot8f(wa0, wb0, xa, xb);
                    sd1 += dot8f(wa1, wb1, xa, xb);
                }
                __syncthreads();
                {
                    const float4* x = (const float4*)stn;
                    float acc = red8(dot8f(rgf[L][0], rgf[L][1], x[2 * p], x[2 * p + 1]));
                    float v = streg * sigm(acc);
                    if (p == 0) {
                        skip[64 * L + r0] = v;
                        if (L < 2) xcat[r0] = v;
                    }
                }
                __syncthreads();
            }

            // ---- J (mini): add o3 part (m=2), finalize sdv ----
            float sdva[2];
            {
                float4 wa0 = __ldg(&wsdf0[32 + 2 * p]), wb0 = __ldg(&wsdf0[32 + 2 * p + 1]);
                float4 wa1 = __ldg(&wsdf1[32 + 2 * p]), wb1 = __ldg(&wsdf1[32 + 2 * p + 1]);
                const float4* xm = (const float4*)(skip + 128);
                float4 xa = xm[2 * p], xb = xm[2 * p + 1];
                sd0 += dot8f(wa0, wb0, xa, xb);
                sd1 += dot8f(wa1, wb1, xa, xb);
                sdva[0] = tanh_f(red8(sd0));
                sdva[1] = tanh_f(red8(sd1));
                if (p == 0) { sdv[r0] = sdva[0]; sdv[64 + r0] = sdva[1]; }
            }
            __syncthreads();

            // ---- K: sov = sdv * sigm(Wsg @ sdv)   (register fp16)
            {
                const float4* x = (const float4*)sdv;
                float4 xa0 = x[2 * p], xa1 = x[2 * p + 1];
                float4 xb0 = x[2 * p + 16], xb1 = x[2 * p + 17];
                #pragma unroll
                for (int it = 0; it < 2; it++) {
                    float acc = dot8h(rsgh[it][0], xa0, xa1) + dot8h(rsgh[it][1], xb0, xb1);
                    acc = red8(acc);
                    if (p == 0) sov[r0 + 64 * it] = sdva[it] * sigm(acc);
                }
            }
            __syncthreads();

            // ---- L: out = tanh(Wout @ sov); emit + ring update   (register fp16)
            {
                const float4* x = (const float4*)sov;
                float acc = dot8h(routh[0], x[2 * p], x[2 * p + 1])
                          + dot8h(routh[1], x[2 * p + 16], x[2 * p + 17]);
                float out = tanh_f(red8(acc));
                if (p == 0) {
                    outp[(long)b * (NFRAMES * 4 * S) + tf * (4 * S) + k * S + r0] = out;
                    ring[(head + r0) & 511] = out;
                }
            }
            head = (head + 64) & 511;
            pb ^= 1;
            __syncthreads();
        }
    }
}

extern "C" void kernel_launch(void* const* d_in, const int* in_sizes, int n_in,
                              void* d_out, int out_size)
{
    const float* feats = (const float*)d_in[0];
    const float* glob  = (const float*)d_in[1];
    const float* prev0 = (const float*)d_in[2];
    const float* Wc1   = (const float*)d_in[3];
    const float* Wc2   = (const float*)d_in[4];
    const float* Wc3   = (const float*)d_in[5];
    const float* Wfw   = (const float*)d_in[6];
    const float* Wfw_g = (const float*)d_in[7];
    const float* Wih1  = (const float*)d_in[8];
    const float* Whh1  = (const float*)d_in[9];
    const float* Wih2  = (const float*)d_in[10];
    const float* Whh2  = (const float*)d_in[11];
    const float* Wih3  = (const float*)d_in[12];
    const float* Whh3  = (const float*)d_in[13];
    const float* Wg1   = (const float*)d_in[14];
    const float* Wg2   = (const float*)d_in[15];
    const float* Wg3   = (const float*)d_in[16];
    const float* Wsg   = (const float*)d_in[17];
    const float* Wsd   = (const float*)d_in[18];
    const float* Wout  = (const float*)d_in[19];
    float* outp = (float*)d_out;

    static bool attr_set = false;
    if (!attr_set) {
        cudaFuncSetAttribute(fargan_kernel,
                             cudaFuncAttributeMaxDynamicSharedMemorySize, DYN_BYTES);
        attr_set = true;
    }

    build_x_kernel<<<NBT, 64>>>(feats, glob);
    gemm_tanh_kernel<<<dim3(4, 100), 256>>>(Wc1, 0, 256, 256);
    gemm_tanh_kernel<<<dim3(4, 100), 256>>>(Wc2, 1, 256, 256);
    gemm_tanh_kernel<<<dim3(8, 100), 256>>>(Wc3, 2, 512, 256);
    fwpre_kernel<<<NBT, 256>>>(Wfw);
    fargan_kernel<<<BATCH, NTH, DYN_BYTES>>>(prev0,
                                  Wfw, Wfw_g,
                                  Wih1, Whh1, Wih2, Whh2, Wih3, Whh3,
                                  Wg1, Wg2, Wg3, Wsg, Wsd, Wout, outp);
}

// round 12
// speedup vs baseline: 1.5365x; 1.0756x over previous
#include <cuda_runtime.h>
#include <cuda_fp16.h>
#include <math.h>

#define S       64
#define LPREV   512
#define NF      193
#define NFRAMES 100
#define BATCH   64
#define NTH     512
#define NBT     (BATCH * NFRAMES)   // 6400

// ---------------- scratch (static device allocations) ----------------
__device__ float  g_X [NBT * 256];
__device__ float  g_H1[NBT * 256];
__device__ float  g_H2[NBT * 256];
__device__ float  g_C [NBT * 512];
__device__ float  g_fwpre[NBT * 4 * 64];
__device__ int    g_period[NBT];
__device__ __half g_hWsd[128 * 320];

__device__ __forceinline__ float sigm(float x)   { return __fdividef(1.f, 1.f + __expf(-x)); }
__device__ __forceinline__ float tanh_f(float x) { return fmaf(2.f, __fdividef(1.f, 1.f + __expf(-2.f * x)), -1.f); }
__device__ __forceinline__ float red8(float v) {
    v += __shfl_xor_sync(0xffffffffu, v, 1);
    v += __shfl_xor_sync(0xffffffffu, v, 2);
    v += __shfl_xor_sync(0xffffffffu, v, 4);
    return v;
}
// dot of 8 fp16 weights (one uint4) with 8 fp32 inputs (two float4)
__device__ __forceinline__ float dot8h(uint4 u, float4 xa, float4 xb) {
    float2 f0 = __half22float2(*reinterpret_cast<__half2*>(&u.x));
    float2 f1 = __half22float2(*reinterpret_cast<__half2*>(&u.y));
    float2 f2 = __half22float2(*reinterpret_cast<__half2*>(&u.z));
    float2 f3 = __half22float2(*reinterpret_cast<__half2*>(&u.w));
    float a = fmaf(f0.x, xa.x, f0.y * xa.y);
    a = fmaf(f1.x, xa.z, a); a = fmaf(f1.y, xa.w, a);
    a = fmaf(f2.x, xb.x, a); a = fmaf(f2.y, xb.y, a);
    a = fmaf(f3.x, xb.z, a); a = fmaf(f3.y, xb.w, a);
    return a;
}
// dot of 8 fp32 weights (two float4) with 8 fp32 inputs (two float4)
__device__ __forceinline__ float dot8f(float4 wa, float4 wb, float4 xa, float4 xb) {
    float a = wa.x * xa.x;
    a = fmaf(wa.y, xa.y, a);
    a = fmaf(wa.z, xa.z, a); a = fmaf(wa.w, xa.w, a);
    a = fmaf(wb.x, xb.x, a); a = fmaf(wb.y, xb.y, a);
    a = fmaf(wb.z, xb.z, a); a = fmaf(wb.w, xb.w, a);
    return a;
}
// pack 8 consecutive fp32 -> uint4 of 8 fp16
__device__ __forceinline__ uint4 pack8(const float* __restrict__ s) {
    union { uint4 u; __half2 h[4]; } r;
    r.h[0] = __floats2half2_rn(__ldg(&s[0]), __ldg(&s[1]));
    r.h[1] = __floats2half2_rn(__ldg(&s[2]), __ldg(&s[3]));
    r.h[2] = __floats2half2_rn(__ldg(&s[4]), __ldg(&s[5]));
    r.h[3] = __floats2half2_rn(__ldg(&s[6]), __ldg(&s[7]));
    return r.u;
}

// ---------------- prep kernels ----------------
__global__ void convert_wsd_kernel(const float* __restrict__ Wsd)
{
    int i = blockIdx.x * blockDim.x + threadIdx.x;
    if (i < 128 * 320) g_hWsd[i] = __float2half(Wsd[i]);
}

__global__ void build_x_kernel(const float* __restrict__ feats,
                               const float* __restrict__ glob)
{
    const int bt = blockIdx.x;
    const int b = bt / NFRAMES, t = bt % NFRAMES;
    const float* fb = feats + (long)b * NF * NFRAMES;
    for (int i = threadIdx.x; i < 192; i += blockDim.x)
        g_X[bt * 256 + i] = fb[i * NFRAMES + t];
    for (int i = threadIdx.x; i < 64; i += blockDim.x)
        g_X[bt * 256 + 192 + i] = glob[b * 64 + i];
    if (threadIdx.x == 0)
        g_period[bt] = (int)lrintf(fb[192 * NFRAMES + t]);
}

// C[M,N] = tanh(A[M,K] @ W[N,K]^T); tiles 64x64x64
__global__ __launch_bounds__(256)
void gemm_tanh_kernel(const float* __restrict__ Wt, int layer, int N, int K)
{
    const float* A = (layer == 0) ? g_X : (layer == 1) ? g_H1 : g_H2;
    float*       C = (layer == 0) ? g_H1 : (layer == 1) ? g_H2 : g_C;

    __shared__ float As[64][68];
    __shared__ float Ws[64][68];

    const int tid = threadIdx.x;
    const int m0 = blockIdx.y * 64, n0 = blockIdx.x * 64;
    const int lr = tid >> 2, lc = tid & 3;
    const int ty = tid >> 4, tx = tid & 15;

    float acc[4][4] = {};

    for (int k0 = 0; k0 < K; k0 += 64) {
        const float4* Arow = (const float4*)(A  + (long)(m0 + lr) * K + k0);
        const float4* Wrow = (const float4*)(Wt + (long)(n0 + lr) * K + k0);
        #pragma unroll
        for (int jj = 0; jj < 4; jj++) {
            float4 av = __ldg(&Arow[lc * 4 + jj]);
            float4 wv = __ldg(&Wrow[lc * 4 + jj]);
            int kk = lc * 16 + jj * 4;
            As[kk + 0][lr] = av.x; As[kk + 1][lr] = av.y;
            As[kk + 2][lr] = av.z; As[kk + 3][lr] = av.w;
            Ws[kk + 0][lr] = wv.x; Ws[kk + 1][lr] = wv.y;
            Ws[kk + 2][lr] = wv.z; Ws[kk + 3][lr] = wv.w;
        }
        __syncthreads();
        #pragma unroll
        for (int kk = 0; kk < 64; kk++) {
            float4 a = *(const float4*)&As[kk][ty * 4];
            float4 w = *(const float4*)&Ws[kk][tx * 4];
            acc[0][0] = fmaf(a.x, w.x, acc[0][0]); acc[0][1] = fmaf(a.x, w.y, acc[0][1]);
            acc[0][2] = fmaf(a.x, w.z, acc[0][2]); acc[0][3] = fmaf(a.x, w.w, acc[0][3]);
            acc[1][0] = fmaf(a.y, w.x, acc[1][0]); acc[1][1] = fmaf(a.y, w.y, acc[1][1]);
            acc[1][2] = fmaf(a.y, w.z, acc[1][2]); acc[1][3] = fmaf(a.y, w.w, acc[1][3]);
            acc[2][0] = fmaf(a.z, w.x, acc[2][0]); acc[2][1] = fmaf(a.z, w.y, acc[2][1]);
            acc[2][2] = fmaf(a.z, w.z, acc[2][2]); acc[2][3] = fmaf(a.z, w.w, acc[2][3]);
            acc[3][0] = fmaf(a.w, w.x, acc[3][0]); acc[3][1] = fmaf(a.w, w.y, acc[3][1]);
            acc[3][2] = fmaf(a.w, w.z, acc[3][2]); acc[3][3] = fmaf(a.w, w.w, acc[3][3]);
        }
        __syncthreads();
    }
    #pragma unroll
    for (int i = 0; i < 4; i++)
        #pragma unroll
        for (int j = 0; j < 4; j++)
            C[(long)(m0 + ty * 4 + i) * N + n0 + tx * 4 + j] = tanh_f(acc[i][j]);
}

// fwpre[bt][k][j] = Wfw[j,0:128] @ feat2s(bt,k) + Wfw[j,260:388] @ sfw(bt,k)
__global__ __launch_bounds__(256)
void fwpre_kernel(const float* __restrict__ Wfw)
{
    const int bt = blockIdx.x;
    const int t  = bt % NFRAMES;
    const int tid = threadIdx.x;
    __shared__ float sc[512], sp[512];
    for (int i = tid; i < 512; i += 256) {
        sc[i] = g_C[(long)bt * 512 + i];
        sp[i] = (t > 0) ? g_C[(long)(bt - 1) * 512 + i] : 0.f;
    }
    __syncthreads();
    const int p = tid & 3, row = tid >> 2;
    const float* wr = Wfw + row * 388;
    #pragma unroll
    for (int k = 0; k < 4; k++) {
        const float* sfw = (k == 0) ? sp : sc;
        const int ksf = (k == 0) ? 3 : (k - 1);
        float acc = 0.f;
        #pragma unroll 8
        for (int mm = 0; mm < 32; mm++) {
            int m = p * 32 + mm;
            acc = fmaf(__ldg(&wr[m]),       sc[4 * m + k],    acc);
            acc = fmaf(__ldg(&wr[260 + m]), sfw[4 * m + ksf], acc);
        }
        acc += __shfl_xor_sync(0xffffffffu, acc, 1);
        acc += __shfl_xor_sync(0xffffffffu, acc, 2);
        if (p == 0) g_fwpre[((long)bt * 4 + k) * 64 + row] = acc;
    }
}

// ---------------- serial recurrence ----------------

#define DYN_H16   (3 * 192 * 128 + 3 * 192 * 64)   // Wih x3 + Whh x3 = 110592 halfs
#define DYN_BYTES (DYN_H16 * 2)                    // 221184 B

__global__ __launch_bounds__(NTH, 1)
void fargan_kernel(const float* __restrict__ prev0,
                   const float* __restrict__ Wfw,     // (64,388)
                   const float* __restrict__ Wfw_g,   // (64,64)
                   const float* __restrict__ Wih1,    // (192,128)
                   const float* __restrict__ Whh1,    // (192,64)
                   const float* __restrict__ Wih2,
                   const float* __restrict__ Whh2,
                   const float* __restrict__ Wih3,
                   const float* __restrict__ Whh3,
                   const float* __restrict__ Wg1,     // (64,64)
                   const float* __restrict__ Wg2,
                   const float* __restrict__ Wg3,
                   const float* __restrict__ Wsg,     // (128,128)
                   const float* __restrict__ Wout,    // (64,128)
                   float* __restrict__ outp)          // (B, 25600)
{
    const int b   = blockIdx.x;
    const int tid = threadIdx.x;
    const int p   = tid & 7;        // 8 threads per row
    const int r0  = tid >> 3;       // 64 rows per pass

    extern __shared__ __half dynh[];
    __half* sWih = dynh;                 // 3 x 192 x 128
    __half* sWhh = dynh + 3 * 192 * 128; // 3 x 192 x 64

    __shared__ __align__(16) float ring[LPREV];
    __shared__ __align__(16) float st[2][3][S];      // double-buffered GRU states
    __shared__ __align__(16) float subin[136];       // [prev_sub(64) | lookback(68) | pad(4)]
    __shared__ __align__(16) float fwv[S];
    __shared__ __align__(16) float xcat[2 * S];
    __shared__ __align__(16) float skip[5 * S];      // [o1|o2|o3|fw|psub]
    __shared__ __align__(16) float sdv[2 * S];
    __shared__ __align__(16) float sov[2 * S];
    __shared__ __align__(16) float fwp4[256];
    __shared__ __align__(16) float ghs[3 * 192];     // precomputed Whh@st, [L][it][row]
    __shared__ int period_sh;

    // ---- one-time: stage Wih / Whh as fp16 into smem ----
    {
        const float* src[3] = { Wih1, Wih2, Wih3 };
        #pragma unroll
        for (int m = 0; m < 3; m++)
            for (int i = tid; i < 192 * 128; i += NTH)
                sWih[m * 192 * 128 + i] = __float2half(__ldg(&src[m][i]));
        const float* srh[3] = { Whh1, Whh2, Whh3 };
        #pragma unroll
        for (int m = 0; m < 3; m++)
            for (int i = tid; i < 192 * 64; i += NTH)
                sWhh[m * 192 * 64 + i] = __float2half(__ldg(&srh[m][i]));
    }

    // ---- persistent register weight caches ----
    // Wfw2: cols [128,264) of Wfw, row r0, 17 consecutive floats per thread (fp32)
    float rfw2[17];
    #pragma unroll
    for (int i = 0; i < 17; i++) {
        int col = p * 17 + i;
        rfw2[i] = (col < 132) ? __ldg(&Wfw[r0 * 388 + 128 + col]) : 0.f;
    }
    // gates (Wg1,Wg2,Wg3,Wfwg): fp32, row r0, cols [8p, 8p+8)  (32 regs)
    float4 rgf[4][2];
    {
        const float* gsrc[4] = { Wg1, Wg2, Wg3, Wfw_g };
        #pragma unroll
        for (int m = 0; m < 4; m++) {
            const float4* w = (const float4*)(gsrc[m] + r0 * 64 + 8 * p);
            rgf[m][0] = __ldg(&w[0]);
            rgf[m][1] = __ldg(&w[1]);
        }
    }
    // Wsg: 128x128 fp16, rows r0 and r0+64, chunks p and p+8
    uint4 rsgh[2][2];
    #pragma unroll
    for (int it = 0; it < 2; it++) {
        rsgh[it][0] = pack8(Wsg + (r0 + 64 * it) * 128 + 8 * p);
        rsgh[it][1] = pack8(Wsg + (r0 + 64 * it) * 128 + 8 * (p + 8));
    }
    // Wout: 64x128 fp16, row r0, chunks p and p+8
    uint4 routh[2];
    routh[0] = pack8(Wout + r0 * 128 + 8 * p);
    routh[1] = pack8(Wout + r0 * 128 + 8 * (p + 8));

    // Wsd chunk pointers: per part m (0..4), thread covers rows r0 / r0+64, cols [64m+8p, +8)
    const uint4* wsd0 = (const uint4*)(g_hWsd + r0 * 320) + p;         // + 8*m
    const uint4* wsd1 = (const uint4*)(g_hWsd + (r0 + 64) * 320) + p;  // + 8*m

    // ---- init state ----
    for (int i = tid; i < LPREV; i += NTH) ring[i] = prev0[b * LPREV + i];
    if (tid < 3 * S) st[0][tid >> 6][tid & 63] = 0.f;
    if (tid >= 132 && tid < 136) subin[tid] = 0.f;
    int head = 0;
    int pb = 0;
    __syncthreads();

    for (int tf = 0; tf < NFRAMES; tf++) {
        const int bt = b * NFRAMES + tf;
        // ---- frame top: stage fwpre for all 4 subframes + period ----
        if (tid < 256) fwp4[tid] = __ldg(&g_fwpre[(long)bt * 256 + tid]);
        if (tid == 0) period_sh = __ldg(&g_period[bt]);
        __syncthreads();
        const int period = period_sh;

        for (int k = 0; k < 4; k++) {
            float sd0 = 0.f, sd1 = 0.f;   // incremental Wsd @ skip accumulators

            // ---- A: build [prev_sub | lookback], seed tails ----
            if (tid < 132) {
                if (tid < 64) {
                    float v = ring[(head + 448 + tid) & 511];
                    subin[tid] = v;
                    skip[256 + tid] = v;
                    xcat[64 + tid] = v;
                } else {
                    int i = tid - 64;
                    int idx = LPREV - period + i - 2;
                    if (idx >= LPREV) idx -= period;
                    subin[tid] = ring[(head + idx) & 511];
                }
            }
            __syncthreads();

            // ---- B: fwraw = tanh(Wfw2 @ subin + fwpre)  [+ Wsd psub part + gh1]
            float fwreg;
            {
                uint4 w0 = __ldg(wsd0 + 32), w1 = __ldg(wsd1 + 32);   // part m=4 (psub)
                float a = 0.f;
                #pragma unroll
                for (int i = 0; i < 17; i++)
                    a = fmaf(rfw2[i], subin[p * 17 + i], a);
                fwreg = tanh_f(red8(a) + fwp4[k * 64 + r0]);
                if (p == 0) fwv[r0] = fwreg;
                const float4* xs = (const float4*)(skip + 256);
                sd0 += dot8h(w0, xs[2 * p], xs[2 * p + 1]);
                sd1 += dot8h(w1, xs[2 * p], xs[2 * p + 1]);

                // gh1 precompute: Whh1 @ st[pb][0] (read-only this subframe)
                const float4* sx = (const float4*)st[pb][0];
                float4 sv0 = sx[2 * p], sv1 = sx[2 * p + 1];
                #pragma unroll
                for (int it = 0; it < 3; it++) {
                    const uint4* wh = (const uint4*)(sWhh + (r0 + (it << 6)) * 64);
                    float g = red8(dot8h(wh[p], sv0, sv1));
                    if (p == 0) ghs[(it << 6) + r0] = g;
                }
            }
            __syncthreads();

            // ---- C: fw = fwraw * sigm(Wfwg @ fwv)  [+ gh2, gh3 precompute]
            {
                const float4* x = (const float4*)fwv;
                float acc = red8(dot8f(rgf[3][0], rgf[3][1], x[2 * p], x[2 * p + 1]));
                fwreg = fwreg * sigm(acc);
                if (p == 0) { skip[192 + r0] = fwreg; xcat[r0] = fwreg; }

                #pragma unroll
                for (int L2 = 1; L2 < 3; L2++) {
                    const float4* sx = (const float4*)st[pb][L2];
                    float4 sv0 = sx[2 * p], sv1 = sx[2 * p + 1];
                    const __half* WH = sWhh + L2 * 192 * 64;
                    #pragma unroll
                    for (int it = 0; it < 3; it++) {
                        const uint4* wh = (const uint4*)(WH + (r0 + (it << 6)) * 64);
                        float g = red8(dot8h(wh[p], sv0, sv1));
                        if (p == 0) ghs[L2 * 192 + (it << 6) + r0] = g;
                    }
                }
            }
            __syncthreads();

            // ---- 3 x (GRU fused + GLU fused); gh read from ghs ----
            #pragma unroll
            for (int L = 0; L < 3; L++) {
                const __half* WI = sWih + L * 192 * 128;
                const float* sto = st[pb][L];
                float* stn = st[pb ^ 1][L];
                float streg;
                {
                    // Wsd part for this stage: L=0 -> fw (m=3), L=1 -> o1 (m=0), L=2 -> o2 (m=1)
                    const int m = (L == 0) ? 3 : (L - 1);
                    uint4 w0 = __ldg(wsd0 + 8 * m), w1 = __ldg(wsd1 + 8 * m);

                    const float4* x = (const float4*)xcat;
                    float4 xa0 = x[2 * p], xa1 = x[2 * p + 1];
                    float4 xb0 = x[2 * p + 16], xb1 = x[2 * p + 17];
                    float gi[3];
                    #pragma unroll
                    for (int it = 0; it < 3; it++) {
                        const uint4* wi = (const uint4*)(WI + (r0 + (it << 6)) * 128);
                        float a = dot8h(wi[p], xa0, xa1) + dot8h(wi[p + 8], xb0, xb1);
                        gi[it] = red8(a);
                    }
                    float g0 = ghs[L * 192 + r0];
                    float g1 = ghs[L * 192 + 64 + r0];
                    float g2 = ghs[L * 192 + 128 + r0];
                    float r = sigm(gi[0] + g0);
                    float z = sigm(gi[1] + g1);
                    float n = tanh_f(gi[2] + r * g2);
                    streg = (1.f - z) * n + z * sto[r0];
                    if (p == 0) stn[r0] = streg;

                    const float4* xm = (const float4*)(skip + 64 * m);
                    sd0 += dot8h(w0, xm[2 * p], xm[2 * p + 1]);
                    sd1 += dot8h(w1, xm[2 * p], xm[2 * p + 1]);
                }
                __syncthreads();
                {
                    const float4* x = (const float4*)stn;
                    float acc = red8(dot8f(rgf[L][0], rgf[L][1], x[2 * p], x[2 * p + 1]));
                    float v = streg * sigm(acc);
                    if (p == 0) {
                        skip[64 * L + r0] = v;
                        if (L < 2) xcat[r0] = v;
                    }
                }
                __syncthreads();
            }

            // ---- J (mini): add o3 part, finalize sdv ----
            float sdva[2];
            {
                uint4 w0 = __ldg(wsd0 + 16), w1 = __ldg(wsd1 + 16);   // part m=2 (o3)
                const float4* xm = (const float4*)(skip + 128);
                sd0 += dot8h(w0, xm[2 * p], xm[2 * p + 1]);
                sd1 += dot8h(w1, xm[2 * p], xm[2 * p + 1]);
                sdva[0] = tanh_f(red8(sd0));
                sdva[1] = tanh_f(red8(sd1));
                if (p == 0) { sdv[r0] = sdva[0]; sdv[64 + r0] = sdva[1]; }
            }
            __syncthreads();

            // ---- K: sov = sdv * sigm(Wsg @ sdv)   (register fp16)
            {
                const float4* x = (const float4*)sdv;
                float4 xa0 = x[2 * p], xa1 = x[2 * p + 1];
                float4 xb0 = x[2 * p + 16], xb1 = x[2 * p + 17];
                #pragma unroll
                for (int it = 0; it < 2; it++) {
                    float acc = dot8h(rsgh[it][0], xa0, xa1) + dot8h(rsgh[it][1], xb0, xb1);
                    acc = red8(acc);
                    if (p == 0) sov[r0 + 64 * it] = sdva[it] * sigm(acc);
                }
            }
            __syncthreads();

            // ---- L: out = tanh(Wout @ sov); emit + ring update   (register fp16)
            {
                const float4* x = (const float4*)sov;
                float acc = dot8h(routh[0], x[2 * p], x[2 * p + 1])
                          + dot8h(routh[1], x[2 * p + 16], x[2 * p + 17]);
                float out = tanh_f(red8(acc));
                if (p == 0) {
                    outp[(long)b * (NFRAMES * 4 * S) + tf * (4 * S) + k * S + r0] = out;
                    ring[(head + r0) & 511] = out;
                }
            }
            head = (head + 64) & 511;
            pb ^= 1;
            __syncthreads();
        }
    }
}

extern "C" void kernel_launch(void* const* d_in, const int* in_sizes, int n_in,
                              void* d_out, int out_size)
{
    const float* feats = (const float*)d_in[0];
    const float* glob  = (const float*)d_in[1];
    const float* prev0 = (const float*)d_in[2];
    const float* Wc1   = (const float*)d_in[3];
    const float* Wc2   = (const float*)d_in[4];
    const float* Wc3   = (const float*)d_in[5];
    const float* Wfw   = (const float*)d_in[6];
    const float* Wfw_g = (const float*)d_in[7];
    const float* Wih1  = (const float*)d_in[8];
    const float* Whh1  = (const float*)d_in[9];
    const float* Wih2  = (const float*)d_in[10];
    const float* Whh2  = (const float*)d_in[11];
    const float* Wih3  = (const float*)d_in[12];
    const float* Whh3  = (const float*)d_in[13];
    const float* Wg1   = (const float*)d_in[14];
    const float* Wg2   = (const float*)d_in[15];
    const float* Wg3   = (const float*)d_in[16];
    const float* Wsg   = (const float*)d_in[17];
    const float* Wsd   = (const float*)d_in[18];
    const float* Wout  = (const float*)d_in[19];
    float* outp = (float*)d_out;

    static bool attr_set = false;
    if (!attr_set) {
        cudaFuncSetAttribute(fargan_kernel,
                             cudaFuncAttributeMaxDynamicSharedMemorySize, DYN_BYTES);
        attr_set = true;
    }

    convert_wsd_kernel<<<(128 * 320 + 255) / 256, 256>>>(Wsd);
    build_x_kernel<<<NBT, 64>>>(feats, glob);
    gemm_tanh_kernel<<<dim3(4, 100), 256>>>(Wc1, 0, 256, 256);
    gemm_tanh_kernel<<<dim3(4, 100), 256>>>(Wc2, 1, 256, 256);
    gemm_tanh_kernel<<<dim3(8, 100), 256>>>(Wc3, 2, 512, 256);
    fwpre_kernel<<<NBT, 256>>>(Wfw);
    fargan_kernel<<<BATCH, NTH, DYN_BYTES>>>(prev0,
                                  Wfw, Wfw_g,
                                  Wih1, Whh1, Wih2, Whh2, Wih3, Whh3,
                                  Wg1, Wg2, Wg3, Wsg, Wout, outp);
}

// round 13
// speedup vs baseline: 2.0522x; 1.3356x over previous
#include <cuda_runtime.h>
#include <cuda_fp16.h>
#include <math.h>

#define S       64
#define LPREV   512
#define NF      193
#define NFRAMES 100
#define BATCH   64
#define NTH     512
#define NBT     (BATCH * NFRAMES)   // 6400

// ---------------- scratch (static device allocations) ----------------
__device__ float  g_X [NBT * 256];
__device__ float  g_H1[NBT * 256];
__device__ float  g_H2[NBT * 256];
__device__ float  g_C [NBT * 512];
__device__ float  g_fwpre[NBT * 4 * 64];
__device__ int    g_period[NBT];
__device__ __half g_hWsd[128 * 320];

__device__ __forceinline__ float sigm(float x)   { return __fdividef(1.f, 1.f + __expf(-x)); }
__device__ __forceinline__ float tanh_f(float x) { return fmaf(2.f, __fdividef(1.f, 1.f + __expf(-2.f * x)), -1.f); }
__device__ __forceinline__ float red8(float v) {
    v += __shfl_xor_sync(0xffffffffu, v, 1);
    v += __shfl_xor_sync(0xffffffffu, v, 2);
    v += __shfl_xor_sync(0xffffffffu, v, 4);
    return v;
}
// half2 MAC of 8 fp16 weights (uint4) with 8 fp16 activations (uint4)
__device__ __forceinline__ __half2 dot8hh(uint4 w, uint4 x, __half2 acc) {
    const __half2* wh = reinterpret_cast<const __half2*>(&w);
    const __half2* xh = reinterpret_cast<const __half2*>(&x);
    acc = __hfma2(wh[0], xh[0], acc);
    acc = __hfma2(wh[1], xh[1], acc);
    acc = __hfma2(wh[2], xh[2], acc);
    acc = __hfma2(wh[3], xh[3], acc);
    return acc;
}
__device__ __forceinline__ float hsum2f(__half2 a) {
    float2 f = __half22float2(a);
    return f.x + f.y;
}
// dot of 8 fp32 weights (two float4) with 8 fp32 inputs (two float4)
__device__ __forceinline__ float dot8f(float4 wa, float4 wb, float4 xa, float4 xb) {
    float a = wa.x * xa.x;
    a = fmaf(wa.y, xa.y, a);
    a = fmaf(wa.z, xa.z, a); a = fmaf(wa.w, xa.w, a);
    a = fmaf(wb.x, xb.x, a); a = fmaf(wb.y, xb.y, a);
    a = fmaf(wb.z, xb.z, a); a = fmaf(wb.w, xb.w, a);
    return a;
}
// pack 8 consecutive fp32 -> uint4 of 8 fp16
__device__ __forceinline__ uint4 pack8(const float* __restrict__ s) {
    union { uint4 u; __half2 h[4]; } r;
    r.h[0] = __floats2half2_rn(__ldg(&s[0]), __ldg(&s[1]));
    r.h[1] = __floats2half2_rn(__ldg(&s[2]), __ldg(&s[3]));
    r.h[2] = __floats2half2_rn(__ldg(&s[4]), __ldg(&s[5]));
    r.h[3] = __floats2half2_rn(__ldg(&s[6]), __ldg(&s[7]));
    return r.u;
}

// ---------------- prep kernels ----------------
__global__ void convert_wsd_kernel(const float* __restrict__ Wsd)
{
    int i = blockIdx.x * blockDim.x + threadIdx.x;
    if (i < 128 * 320) g_hWsd[i] = __float2half(Wsd[i]);
}

__global__ void build_x_kernel(const float* __restrict__ feats,
                               const float* __restrict__ glob)
{
    const int bt = blockIdx.x;
    const int b = bt / NFRAMES, t = bt % NFRAMES;
    const float* fb = feats + (long)b * NF * NFRAMES;
    for (int i = threadIdx.x; i < 192; i += blockDim.x)
        g_X[bt * 256 + i] = fb[i * NFRAMES + t];
    for (int i = threadIdx.x; i < 64; i += blockDim.x)
        g_X[bt * 256 + 192 + i] = glob[b * 64 + i];
    if (threadIdx.x == 0)
        g_period[bt] = (int)lrintf(fb[192 * NFRAMES + t]);
}

// C[M,N] = tanh(A[M,K] @ W[N,K]^T); tiles 64x64x64
__global__ __launch_bounds__(256)
void gemm_tanh_kernel(const float* __restrict__ Wt, int layer, int N, int K)
{
    const float* A = (layer == 0) ? g_X : (layer == 1) ? g_H1 : g_H2;
    float*       C = (layer == 0) ? g_H1 : (layer == 1) ? g_H2 : g_C;

    __shared__ float As[64][68];
    __shared__ float Ws[64][68];

    const int tid = threadIdx.x;
    const int m0 = blockIdx.y * 64, n0 = blockIdx.x * 64;
    const int lr = tid >> 2, lc = tid & 3;
    const int ty = tid >> 4, tx = tid & 15;

    float acc[4][4] = {};

    for (int k0 = 0; k0 < K; k0 += 64) {
        const float4* Arow = (const float4*)(A  + (long)(m0 + lr) * K + k0);
        const float4* Wrow = (const float4*)(Wt + (long)(n0 + lr) * K + k0);
        #pragma unroll
        for (int jj = 0; jj < 4; jj++) {
            float4 av = __ldg(&Arow[lc * 4 + jj]);
            float4 wv = __ldg(&Wrow[lc * 4 + jj]);
            int kk = lc * 16 + jj * 4;
            As[kk + 0][lr] = av.x; As[kk + 1][lr] = av.y;
            As[kk + 2][lr] = av.z; As[kk + 3][lr] = av.w;
            Ws[kk + 0][lr] = wv.x; Ws[kk + 1][lr] = wv.y;
            Ws[kk + 2][lr] = wv.z; Ws[kk + 3][lr] = wv.w;
        }
        __syncthreads();
        #pragma unroll
        for (int kk = 0; kk < 64; kk++) {
            float4 a = *(const float4*)&As[kk][ty * 4];
            float4 w = *(const float4*)&Ws[kk][tx * 4];
            acc[0][0] = fmaf(a.x, w.x, acc[0][0]); acc[0][1] = fmaf(a.x, w.y, acc[0][1]);
            acc[0][2] = fmaf(a.x, w.z, acc[0][2]); acc[0][3] = fmaf(a.x, w.w, acc[0][3]);
            acc[1][0] = fmaf(a.y, w.x, acc[1][0]); acc[1][1] = fmaf(a.y, w.y, acc[1][1]);
            acc[1][2] = fmaf(a.y, w.z, acc[1][2]); acc[1][3] = fmaf(a.y, w.w, acc[1][3]);
            acc[2][0] = fmaf(a.z, w.x, acc[2][0]); acc[2][1] = fmaf(a.z, w.y, acc[2][1]);
            acc[2][2] = fmaf(a.z, w.z, acc[2][2]); acc[2][3] = fmaf(a.z, w.w, acc[2][3]);
            acc[3][0] = fmaf(a.w, w.x, acc[3][0]); acc[3][1] = fmaf(a.w, w.y, acc[3][1]);
            acc[3][2] = fmaf(a.w, w.z, acc[3][2]); acc[3][3] = fmaf(a.w, w.w, acc[3][3]);
        }
        __syncthreads();
    }
    #pragma unroll
    for (int i = 0; i < 4; i++)
        #pragma unroll
        for (int j = 0; j < 4; j++)
            C[(long)(m0 + ty * 4 + i) * N + n0 + tx * 4 + j] = tanh_f(acc[i][j]);
}

// fwpre[bt][k][j] = Wfw[j,0:128] @ feat2s(bt,k) + Wfw[j,260:388] @ sfw(bt,k)
__global__ __launch_bounds__(256)
void fwpre_kernel(const float* __restrict__ Wfw)
{
    const int bt = blockIdx.x;
    const int t  = bt % NFRAMES;
    const int tid = threadIdx.x;
    __shared__ float sc[512], sp[512];
    for (int i = tid; i < 512; i += 256) {
        sc[i] = g_C[(long)bt * 512 + i];
        sp[i] = (t > 0) ? g_C[(long)(bt - 1) * 512 + i] : 0.f;
    }
    __syncthreads();
    const int p = tid & 3, row = tid >> 2;
    const float* wr = Wfw + row * 388;
    #pragma unroll
    for (int k = 0; k < 4; k++) {
        const float* sfw = (k == 0) ? sp : sc;
        const int ksf = (k == 0) ? 3 : (k - 1);
        float acc = 0.f;
        #pragma unroll 8
        for (int mm = 0; mm < 32; mm++) {
            int m = p * 32 + mm;
            acc = fmaf(__ldg(&wr[m]),       sc[4 * m + k],    acc);
            acc = fmaf(__ldg(&wr[260 + m]), sfw[4 * m + ksf], acc);
        }
        acc += __shfl_xor_sync(0xffffffffu, acc, 1);
        acc += __shfl_xor_sync(0xffffffffu, acc, 2);
        if (p == 0) g_fwpre[((long)bt * 4 + k) * 64 + row] = acc;
    }
}

// ---------------- serial recurrence ----------------

#define DYN_H16   (3 * 192 * 128 + 3 * 192 * 64)   // Wih x3 + Whh x3 = 110592 halfs
#define DYN_BYTES (DYN_H16 * 2)                    // 221184 B

__global__ __launch_bounds__(NTH, 1)
void fargan_kernel(const float* __restrict__ prev0,
                   const float* __restrict__ Wfw,     // (64,388)
                   const float* __restrict__ Wfw_g,   // (64,64)
                   const float* __restrict__ Wih1,    // (192,128)
                   const float* __restrict__ Whh1,    // (192,64)
                   const float* __restrict__ Wih2,
                   const float* __restrict__ Whh2,
                   const float* __restrict__ Wih3,
                   const float* __restrict__ Whh3,
                   const float* __restrict__ Wg1,     // (64,64)
                   const float* __restrict__ Wg2,
                   const float* __restrict__ Wg3,
                   const float* __restrict__ Wsg,     // (128,128)
                   const float* __restrict__ Wout,    // (64,128)
                   float* __restrict__ outp)          // (B, 25600)
{
    const int b   = blockIdx.x;
    const int tid = threadIdx.x;
    const int p   = tid & 7;        // 8 threads per row
    const int r0  = tid >> 3;       // 64 rows per pass

    extern __shared__ __half dynh[];
    __half* sWih = dynh;                 // 3 x 192 x 128
    __half* sWhh = dynh + 3 * 192 * 128; // 3 x 192 x 64

    __shared__ __align__(16) float  ring[LPREV];
    __shared__ __align__(16) float  st[2][3][S];     // fp32 recurrent state (double-buffered)
    __shared__ __align__(16) __half sth[2][3][S];    // half copy for Whh dots
    __shared__ __align__(16) float  subin[136];      // fp32 [prev_sub | lookback | pad]
    __shared__ __align__(16) float  fwv[S];          // fp32 (feeds fp32 gate dot)
    __shared__ __align__(16) __half xcath[2 * S];    // half GRU input [fw/o | psub]
    __shared__ __align__(16) __half skiph[5 * S];    // half [o1|o2|o3|fw|psub]
    __shared__ __align__(16) __half sdvh[2 * S];
    __shared__ __align__(16) __half sovh[2 * S];
    __shared__ __align__(16) float  fwp4[256];
    __shared__ int period_sh;

    // ---- one-time: stage Wih / Whh as fp16 into smem ----
    {
        const float* src[3] = { Wih1, Wih2, Wih3 };
        #pragma unroll
        for (int m = 0; m < 3; m++)
            for (int i = tid; i < 192 * 128; i += NTH)
                sWih[m * 192 * 128 + i] = __float2half(__ldg(&src[m][i]));
        const float* srh[3] = { Whh1, Whh2, Whh3 };
        #pragma unroll
        for (int m = 0; m < 3; m++)
            for (int i = tid; i < 192 * 64; i += NTH)
                sWhh[m * 192 * 64 + i] = __float2half(__ldg(&srh[m][i]));
    }

    // ---- persistent register weight caches ----
    // Wfw2: cols [128,264) of Wfw, row r0, 17 consecutive floats per thread (fp32)
    float rfw2[17];
    #pragma unroll
    for (int i = 0; i < 17; i++) {
        int col = p * 17 + i;
        rfw2[i] = (col < 132) ? __ldg(&Wfw[r0 * 388 + 128 + col]) : 0.f;
    }
    // gates (Wg1,Wg2,Wg3,Wfwg): fp32, row r0, cols [8p, 8p+8)  (32 regs)
    float4 rgf[4][2];
    {
        const float* gsrc[4] = { Wg1, Wg2, Wg3, Wfw_g };
        #pragma unroll
        for (int m = 0; m < 4; m++) {
            const float4* w = (const float4*)(gsrc[m] + r0 * 64 + 8 * p);
            rgf[m][0] = __ldg(&w[0]);
            rgf[m][1] = __ldg(&w[1]);
        }
    }
    // Wsg: 128x128 fp16, rows r0 and r0+64, chunks p and p+8
    uint4 rsgh[2][2];
    #pragma unroll
    for (int it = 0; it < 2; it++) {
        rsgh[it][0] = pack8(Wsg + (r0 + 64 * it) * 128 + 8 * p);
        rsgh[it][1] = pack8(Wsg + (r0 + 64 * it) * 128 + 8 * (p + 8));
    }
    // Wout: 64x128 fp16, row r0, chunks p and p+8
    uint4 routh[2];
    routh[0] = pack8(Wout + r0 * 128 + 8 * p);
    routh[1] = pack8(Wout + r0 * 128 + 8 * (p + 8));

    // Wsd chunk pointers: per part m (0..4), thread covers rows r0 / r0+64, cols [64m+8p, +8)
    const uint4* wsd0 = (const uint4*)(g_hWsd + r0 * 320) + p;         // + 8*m
    const uint4* wsd1 = (const uint4*)(g_hWsd + (r0 + 64) * 320) + p;  // + 8*m

    // ---- init state ----
    for (int i = tid; i < LPREV; i += NTH) ring[i] = prev0[b * LPREV + i];
    if (tid < 3 * S) {
        st[0][tid >> 6][tid & 63] = 0.f;
        sth[0][tid >> 6][tid & 63] = __half(0.f);
    }
    if (tid >= 132 && tid < 136) subin[tid] = 0.f;
    int head = 0;
    int pb = 0;
    __syncthreads();

    const __half2 hz = __floats2half2_rn(0.f, 0.f);

    for (int tf = 0; tf < NFRAMES; tf++) {
        const int bt = b * NFRAMES + tf;
        // ---- frame top: stage fwpre for all 4 subframes + period ----
        if (tid < 256) fwp4[tid] = __ldg(&g_fwpre[(long)bt * 256 + tid]);
        if (tid == 0) period_sh = __ldg(&g_period[bt]);
        __syncthreads();
        const int period = period_sh;

        for (int k = 0; k < 4; k++) {
            float sd0 = 0.f, sd1 = 0.f;   // incremental Wsd @ skip accumulators

            // ---- A: build [prev_sub | lookback], seed half tails ----
            if (tid < 132) {
                if (tid < 64) {
                    float v = ring[(head + 448 + tid) & 511];
                    subin[tid] = v;
                    __half hv = __float2half(v);
                    skiph[256 + tid] = hv;
                    xcath[64 + tid] = hv;
                } else {
                    int i = tid - 64;
                    int idx = LPREV - period + i - 2;
                    if (idx >= LPREV) idx -= period;
                    subin[tid] = ring[(head + idx) & 511];
                }
            }
            __syncthreads();

            // ---- B: fwraw = tanh(Wfw2 @ subin + fwpre)  [+ Wsd psub part]
            float fwreg;
            {
                uint4 w0 = __ldg(wsd0 + 32), w1 = __ldg(wsd1 + 32);   // part m=4 (psub)
                float a = 0.f;
                #pragma unroll
                for (int i = 0; i < 17; i++)
                    a = fmaf(rfw2[i], subin[p * 17 + i], a);
                fwreg = tanh_f(red8(a) + fwp4[k * 64 + r0]);
                if (p == 0) fwv[r0] = fwreg;
                uint4 xs = ((const uint4*)(skiph + 256))[p];
                sd0 += hsum2f(dot8hh(w0, xs, hz));
                sd1 += hsum2f(dot8hh(w1, xs, hz));
            }
            __syncthreads();

            // ---- C: fw = fwraw * sigm(Wfwg @ fwv)   (fp32 register gate)
            {
                const float4* x = (const float4*)fwv;
                float acc = red8(dot8f(rgf[3][0], rgf[3][1], x[2 * p], x[2 * p + 1]));
                fwreg = fwreg * sigm(acc);
                if (p == 0) {
                    __half hv = __float2half(fwreg);
                    skiph[192 + r0] = hv;
                    xcath[r0] = hv;
                }
            }
            __syncthreads();

            // ---- 3 x (GRU fused + GLU fused), half2 HFMA2 dots ----
            #pragma unroll
            for (int L = 0; L < 3; L++) {
                const __half* WI = sWih + L * 192 * 128;
                const __half* WH = sWhh + L * 192 * 64;
                const float* sto = st[pb][L];
                float* stn = st[pb ^ 1][L];
                __half* stnh = sth[pb ^ 1][L];
                float streg;
                {
                    // Wsd part for this stage: L=0 -> fw (m=3), L=1 -> o1 (m=0), L=2 -> o2 (m=1)
                    const int m = (L == 0) ? 3 : (L - 1);
                    uint4 w0 = __ldg(wsd0 + 8 * m), w1 = __ldg(wsd1 + 8 * m);

                    const uint4* xh = (const uint4*)xcath;
                    uint4 xa = xh[p], xb = xh[p + 8];
                    uint4 sv = ((const uint4*)sth[pb][L])[p];
                    float gi[3], gh[3];
                    #pragma unroll
                    for (int it = 0; it < 3; it++) {
                        const uint4* wi = (const uint4*)(WI + (r0 + (it << 6)) * 128);
                        __half2 acc = dot8hh(wi[p], xa, hz);
                        acc = dot8hh(wi[p + 8], xb, acc);
                        gi[it] = red8(hsum2f(acc));
                        const uint4* wh = (const uint4*)(WH + (r0 + (it << 6)) * 64);
                        gh[it] = red8(hsum2f(dot8hh(wh[p], sv, hz)));
                    }
                    float r = sigm(gi[0] + gh[0]);
                    float z = sigm(gi[1] + gh[1]);
                    float n = tanh_f(gi[2] + r * gh[2]);
                    streg = (1.f - z) * n + z * sto[r0];
                    if (p == 0) {
                        stn[r0] = streg;
                        stnh[r0] = __float2half(streg);
                    }

                    uint4 xm = ((const uint4*)(skiph + 64 * m))[p];
                    sd0 += hsum2f(dot8hh(w0, xm, hz));
                    sd1 += hsum2f(dot8hh(w1, xm, hz));
                }
                __syncthreads();
                {
                    const float4* x = (const float4*)stn;
                    float acc = red8(dot8f(rgf[L][0], rgf[L][1], x[2 * p], x[2 * p + 1]));
                    float v = streg * sigm(acc);
                    if (p == 0) {
                        __half hv = __float2half(v);
                        skiph[64 * L + r0] = hv;
                        if (L < 2) xcath[r0] = hv;
                    }
                }
                __syncthreads();
            }

            // ---- J (mini): add o3 part, finalize sdv ----
            float sdva[2];
            {
                uint4 w0 = __ldg(wsd0 + 16), w1 = __ldg(wsd1 + 16);   // part m=2 (o3)
                uint4 xm = ((const uint4*)(skiph + 128))[p];
                sd0 += hsum2f(dot8hh(w0, xm, hz));
                sd1 += hsum2f(dot8hh(w1, xm, hz));
                sdva[0] = tanh_f(red8(sd0));
                sdva[1] = tanh_f(red8(sd1));
                if (p == 0) {
                    sdvh[r0] = __float2half(sdva[0]);
                    sdvh[64 + r0] = __float2half(sdva[1]);
                }
            }
            __syncthreads();

            // ---- K: sov = sdv * sigm(Wsg @ sdv)   (register fp16, half2 dots)
            {
                const uint4* xh = (const uint4*)sdvh;
                uint4 xa = xh[p], xb = xh[p + 8];
                #pragma unroll
                for (int it = 0; it < 2; it++) {
                    __half2 acc = dot8hh(rsgh[it][0], xa, hz);
                    acc = dot8hh(rsgh[it][1], xb, acc);
                    float a = red8(hsum2f(acc));
                    if (p == 0) sovh[r0 + 64 * it] = __float2half(sdva[it] * sigm(a));
                }
            }
            __syncthreads();

            // ---- L: out = tanh(Wout @ sov); emit + ring update ----
            {
                const uint4* xh = (const uint4*)sovh;
                __half2 acc = dot8hh(routh[0], xh[p], hz);
                acc = dot8hh(routh[1], xh[p + 8], acc);
                float out = tanh_f(red8(hsum2f(acc)));
                if (p == 0) {
                    outp[(long)b * (NFRAMES * 4 * S) + tf * (4 * S) + k * S + r0] = out;
                    ring[(head + r0) & 511] = out;
                }
            }
            head = (head + 64) & 511;
            pb ^= 1;
            __syncthreads();
        }
    }
}

extern "C" void kernel_launch(void* const* d_in, const int* in_sizes, int n_in,
                              void* d_out, int out_size)
{
    const float* feats = (const float*)d_in[0];
    const float* glob  = (const float*)d_in[1];
    const float* prev0 = (const float*)d_in[2];
    const float* Wc1   = (const float*)d_in[3];
    const float* Wc2   = (const float*)d_in[4];
    const float* Wc3   = (const float*)d_in[5];
    const float* Wfw   = (const float*)d_in[6];
    const float* Wfw_g = (const float*)d_in[7];
    const float* Wih1  = (const float*)d_in[8];
    const float* Whh1  = (const float*)d_in[9];
    const float* Wih2  = (const float*)d_in[10];
    const float* Whh2  = (const float*)d_in[11];
    const float* Wih3  = (const float*)d_in[12];
    const float* Whh3  = (const float*)d_in[13];
    const float* Wg1   = (const float*)d_in[14];
    const float* Wg2   = (const float*)d_in[15];
    const float* Wg3   = (const float*)d_in[16];
    const float* Wsg   = (const float*)d_in[17];
    const float* Wsd   = (const float*)d_in[18];
    const float* Wout  = (const float*)d_in[19];
    float* outp = (float*)d_out;

    static bool attr_set = false;
    if (!attr_set) {
        cudaFuncSetAttribute(fargan_kernel,
                             cudaFuncAttributeMaxDynamicSharedMemorySize, DYN_BYTES);
        attr_set = true;
    }

    convert_wsd_kernel<<<(128 * 320 + 255) / 256, 256>>>(Wsd);
    build_x_kernel<<<NBT, 64>>>(feats, glob);
    gemm_tanh_kernel<<<dim3(4, 100), 256>>>(Wc1, 0, 256, 256);
    gemm_tanh_kernel<<<dim3(4, 100), 256>>>(Wc2, 1, 256, 256);
    gemm_tanh_kernel<<<dim3(8, 100), 256>>>(Wc3, 2, 512, 256);
    fwpre_kernel<<<NBT, 256>>>(Wfw);
    fargan_kernel<<<BATCH, NTH, DYN_BYTES>>>(prev0,
                                  Wfw, Wfw_g,
                                  Wih1, Whh1, Wih2, Whh2, Wih3, Whh3,
                                  Wg1, Wg2, Wg3, Wsg, Wout, outp);
}

// round 14
// speedup vs baseline: 2.0684x; 1.0079x over previous
#include <cuda_runtime.h>
#include <cuda_fp16.h>
#include <math.h>

#define S       64
#define LPREV   512
#define NF      193
#define NFRAMES 100
#define BATCH   64
#define NTH     512
#define NBT     (BATCH * NFRAMES)   // 6400

// ---------------- scratch (static device allocations) ----------------
__device__ float  g_X [NBT * 256];
__device__ float  g_H1[NBT * 256];
__device__ float  g_H2[NBT * 256];
__device__ float  g_C [NBT * 512];
__device__ float  g_fwpre[NBT * 4 * 64];
__device__ int    g_period[NBT];
__device__ __half g_hWsd[128 * 320];

__device__ __forceinline__ float sigm(float x)   { return __fdividef(1.f, 1.f + __expf(-x)); }
__device__ __forceinline__ float tanh_f(float x) { return fmaf(2.f, __fdividef(1.f, 1.f + __expf(-2.f * x)), -1.f); }
__device__ __forceinline__ float red8(float v) {
    v += __shfl_xor_sync(0xffffffffu, v, 1);
    v += __shfl_xor_sync(0xffffffffu, v, 2);
    v += __shfl_xor_sync(0xffffffffu, v, 4);
    return v;
}
// half2 MAC of 8 fp16 weights (uint4) with 8 fp16 activations (uint4)
__device__ __forceinline__ __half2 dot8hh(uint4 w, uint4 x, __half2 acc) {
    const __half2* wh = reinterpret_cast<const __half2*>(&w);
    const __half2* xh = reinterpret_cast<const __half2*>(&x);
    acc = __hfma2(wh[0], xh[0], acc);
    acc = __hfma2(wh[1], xh[1], acc);
    acc = __hfma2(wh[2], xh[2], acc);
    acc = __hfma2(wh[3], xh[3], acc);
    return acc;
}
__device__ __forceinline__ float hsum2f(__half2 a) {
    float2 f = __half22float2(a);
    return f.x + f.y;
}
// dot of 8 fp32 weights (two float4) with 8 fp32 inputs (two float4)
__device__ __forceinline__ float dot8f(float4 wa, float4 wb, float4 xa, float4 xb) {
    float a = wa.x * xa.x;
    a = fmaf(wa.y, xa.y, a);
    a = fmaf(wa.z, xa.z, a); a = fmaf(wa.w, xa.w, a);
    a = fmaf(wb.x, xb.x, a); a = fmaf(wb.y, xb.y, a);
    a = fmaf(wb.z, xb.z, a); a = fmaf(wb.w, xb.w, a);
    return a;
}
// pack 8 consecutive fp32 -> uint4 of 8 fp16
__device__ __forceinline__ uint4 pack8(const float* __restrict__ s) {
    union { uint4 u; __half2 h[4]; } r;
    r.h[0] = __floats2half2_rn(__ldg(&s[0]), __ldg(&s[1]));
    r.h[1] = __floats2half2_rn(__ldg(&s[2]), __ldg(&s[3]));
    r.h[2] = __floats2half2_rn(__ldg(&s[4]), __ldg(&s[5]));
    r.h[3] = __floats2half2_rn(__ldg(&s[6]), __ldg(&s[7]));
    return r.u;
}

// ---------------- prep kernels ----------------
// build_x also converts Wsd -> fp16 (blocks 0..639, 64 elems each) so the
// launch count per call is 6 and ncu -s 5 -c 1 captures fargan_kernel.
__global__ void build_x_kernel(const float* __restrict__ feats,
                               const float* __restrict__ glob,
                               const float* __restrict__ Wsd)
{
    const int bt = blockIdx.x;
    const int b = bt / NFRAMES, t = bt % NFRAMES;
    const float* fb = feats + (long)b * NF * NFRAMES;
    for (int i = threadIdx.x; i < 192; i += blockDim.x)
        g_X[bt * 256 + i] = fb[i * NFRAMES + t];
    for (int i = threadIdx.x; i < 64; i += blockDim.x)
        g_X[bt * 256 + 192 + i] = glob[b * 64 + i];
    if (threadIdx.x == 0)
        g_period[bt] = (int)lrintf(fb[192 * NFRAMES + t]);
    if (bt < 640) {
        int i = bt * 64 + threadIdx.x;
        if (threadIdx.x < 64 && i < 128 * 320)
            g_hWsd[i] = __float2half(Wsd[i]);
    }
}

// C[M,N] = tanh(A[M,K] @ W[N,K]^T); tiles 64x64x64
__global__ __launch_bounds__(256)
void gemm_tanh_kernel(const float* __restrict__ Wt, int layer, int N, int K)
{
    const float* A = (layer == 0) ? g_X : (layer == 1) ? g_H1 : g_H2;
    float*       C = (layer == 0) ? g_H1 : (layer == 1) ? g_H2 : g_C;

    __shared__ float As[64][68];
    __shared__ float Ws[64][68];

    const int tid = threadIdx.x;
    const int m0 = blockIdx.y * 64, n0 = blockIdx.x * 64;
    const int lr = tid >> 2, lc = tid & 3;
    const int ty = tid >> 4, tx = tid & 15;

    float acc[4][4] = {};

    for (int k0 = 0; k0 < K; k0 += 64) {
        const float4* Arow = (const float4*)(A  + (long)(m0 + lr) * K + k0);
        const float4* Wrow = (const float4*)(Wt + (long)(n0 + lr) * K + k0);
        #pragma unroll
        for (int jj = 0; jj < 4; jj++) {
            float4 av = __ldg(&Arow[lc * 4 + jj]);
            float4 wv = __ldg(&Wrow[lc * 4 + jj]);
            int kk = lc * 16 + jj * 4;
            As[kk + 0][lr] = av.x; As[kk + 1][lr] = av.y;
            As[kk + 2][lr] = av.z; As[kk + 3][lr] = av.w;
            Ws[kk + 0][lr] = wv.x; Ws[kk + 1][lr] = wv.y;
            Ws[kk + 2][lr] = wv.z; Ws[kk + 3][lr] = wv.w;
        }
        __syncthreads();
        #pragma unroll
        for (int kk = 0; kk < 64; kk++) {
            float4 a = *(const float4*)&As[kk][ty * 4];
            float4 w = *(const float4*)&Ws[kk][tx * 4];
            acc[0][0] = fmaf(a.x, w.x, acc[0][0]); acc[0][1] = fmaf(a.x, w.y, acc[0][1]);
            acc[0][2] = fmaf(a.x, w.z, acc[0][2]); acc[0][3] = fmaf(a.x, w.w, acc[0][3]);
            acc[1][0] = fmaf(a.y, w.x, acc[1][0]); acc[1][1] = fmaf(a.y, w.y, acc[1][1]);
            acc[1][2] = fmaf(a.y, w.z, acc[1][2]); acc[1][3] = fmaf(a.y, w.w, acc[1][3]);
            acc[2][0] = fmaf(a.z, w.x, acc[2][0]); acc[2][1] = fmaf(a.z, w.y, acc[2][1]);
            acc[2][2] = fmaf(a.z, w.z, acc[2][2]); acc[2][3] = fmaf(a.z, w.w, acc[2][3]);
            acc[3][0] = fmaf(a.w, w.x, acc[3][0]); acc[3][1] = fmaf(a.w, w.y, acc[3][1]);
            acc[3][2] = fmaf(a.w, w.z, acc[3][2]); acc[3][3] = fmaf(a.w, w.w, acc[3][3]);
        }
        __syncthreads();
    }
    #pragma unroll
    for (int i = 0; i < 4; i++)
        #pragma unroll
        for (int j = 0; j < 4; j++)
            C[(long)(m0 + ty * 4 + i) * N + n0 + tx * 4 + j] = tanh_f(acc[i][j]);
}

// fwpre[bt][k][j] = Wfw[j,0:128] @ feat2s(bt,k) + Wfw[j,260:388] @ sfw(bt,k)
__global__ __launch_bounds__(256)
void fwpre_kernel(const float* __restrict__ Wfw)
{
    const int bt = blockIdx.x;
    const int t  = bt % NFRAMES;
    const int tid = threadIdx.x;
    __shared__ float sc[512], sp[512];
    for (int i = tid; i < 512; i += 256) {
        sc[i] = g_C[(long)bt * 512 + i];
        sp[i] = (t > 0) ? g_C[(long)(bt - 1) * 512 + i] : 0.f;
    }
    __syncthreads();
    const int p = tid & 3, row = tid >> 2;
    const float* wr = Wfw + row * 388;
    #pragma unroll
    for (int k = 0; k < 4; k++) {
        const float* sfw = (k == 0) ? sp : sc;
        const int ksf = (k == 0) ? 3 : (k - 1);
        float acc = 0.f;
        #pragma unroll 8
        for (int mm = 0; mm < 32; mm++) {
            int m = p * 32 + mm;
            acc = fmaf(__ldg(&wr[m]),       sc[4 * m + k],    acc);
            acc = fmaf(__ldg(&wr[260 + m]), sfw[4 * m + ksf], acc);
        }
        acc += __shfl_xor_sync(0xffffffffu, acc, 1);
        acc += __shfl_xor_sync(0xffffffffu, acc, 2);
        if (p == 0) g_fwpre[((long)bt * 4 + k) * 64 + row] = acc;
    }
}

// ---------------- serial recurrence ----------------

#define DYN_H16   (3 * 192 * 128 + 3 * 192 * 64)   // Wih x3 + Whh x3 = 110592 halfs
#define DYN_BYTES (DYN_H16 * 2)                    // 221184 B

__global__ __launch_bounds__(NTH, 1)
void fargan_kernel(const float* __restrict__ prev0,
                   const float* __restrict__ Wfw,     // (64,388)
                   const float* __restrict__ Wfw_g,   // (64,64)
                   const float* __restrict__ Wih1,    // (192,128)
                   const float* __restrict__ Whh1,    // (192,64)
                   const float* __restrict__ Wih2,
                   const float* __restrict__ Whh2,
                   const float* __restrict__ Wih3,
                   const float* __restrict__ Whh3,
                   const float* __restrict__ Wg1,     // (64,64)
                   const float* __restrict__ Wg2,
                   const float* __restrict__ Wg3,
                   const float* __restrict__ Wsg,     // (128,128)
                   const float* __restrict__ Wout,    // (64,128)
                   float* __restrict__ outp)          // (B, 25600)
{
    const int b   = blockIdx.x;
    const int tid = threadIdx.x;
    const int p   = tid & 7;        // 8 threads per row
    const int r0  = tid >> 3;       // 64 rows per pass

    extern __shared__ __half dynh[];
    __half* sWih = dynh;                 // 3 x 192 x 128
    __half* sWhh = dynh + 3 * 192 * 128; // 3 x 192 x 64

    __shared__ __align__(16) float  ring[LPREV];
    __shared__ __align__(16) float  st[2][3][S];     // fp32 recurrent state (double-buffered)
    __shared__ __align__(16) __half sth[2][3][S];    // half copy for Whh dots
    __shared__ __align__(16) float  subin[160];      // fp32 [prev_sub(64) | lookback(68) | zero pad]
    __shared__ __align__(16) float  fwv[S];          // fp32 (feeds fp32 gate dot)
    __shared__ __align__(16) __half xcath[2 * S];    // half GRU input [fw/o | psub]
    __shared__ __align__(16) __half skiph[5 * S];    // half [o1|o2|o3|fw|psub]
    __shared__ __align__(16) __half sdvh[2 * S];
    __shared__ __align__(16) __half sovh[2 * S];
    __shared__ __align__(16) float  fwp4[256];
    __shared__ int period_sh;

    // ---- one-time: stage Wih / Whh as fp16 into smem ----
    {
        const float* src[3] = { Wih1, Wih2, Wih3 };
        #pragma unroll
        for (int m = 0; m < 3; m++)
            for (int i = tid; i < 192 * 128; i += NTH)
                sWih[m * 192 * 128 + i] = __float2half(__ldg(&src[m][i]));
        const float* srh[3] = { Whh1, Whh2, Whh3 };
        #pragma unroll
        for (int m = 0; m < 3; m++)
            for (int i = tid; i < 192 * 64; i += NTH)
                sWhh[m * 192 * 64 + i] = __float2half(__ldg(&srh[m][i]));
    }

    // ---- persistent register weight caches ----
    // Wfw2 (cols [128,264) of Wfw) as 5 strided float4 chunks: chunk c = p + 8j,
    // covering subin float4-chunk c (window col 4c..4c+4). Zero beyond col 132.
    float4 rfw2v[5];
    #pragma unroll
    for (int j = 0; j < 5; j++) {
        int c = p + 8 * j;
        float e[4];
        #pragma unroll
        for (int q = 0; q < 4; q++) {
            int col = 4 * c + q;   // within 136.. window (subin idx)
            e[q] = (col < 132) ? __ldg(&Wfw[r0 * 388 + 128 + col]) : 0.f;
        }
        rfw2v[j] = make_float4(e[0], e[1], e[2], e[3]);
    }
    // gates (Wg1,Wg2,Wg3,Wfwg): fp32, row r0, cols [8p, 8p+8)  (32 regs)
    float4 rgf[4][2];
    {
        const float* gsrc[4] = { Wg1, Wg2, Wg3, Wfw_g };
        #pragma unroll
        for (int m = 0; m < 4; m++) {
            const float4* w = (const float4*)(gsrc[m] + r0 * 64 + 8 * p);
            rgf[m][0] = __ldg(&w[0]);
            rgf[m][1] = __ldg(&w[1]);
        }
    }
    // Wsg: 128x128 fp16, rows r0 and r0+64, chunks p and p+8
    uint4 rsgh[2][2];
    #pragma unroll
    for (int it = 0; it < 2; it++) {
        rsgh[it][0] = pack8(Wsg + (r0 + 64 * it) * 128 + 8 * p);
        rsgh[it][1] = pack8(Wsg + (r0 + 64 * it) * 128 + 8 * (p + 8));
    }
    // Wout: 64x128 fp16, row r0, chunks p and p+8
    uint4 routh[2];
    routh[0] = pack8(Wout + r0 * 128 + 8 * p);
    routh[1] = pack8(Wout + r0 * 128 + 8 * (p + 8));

    // Wsd chunk pointers: per part m (0..4), thread covers rows r0 / r0+64, cols [64m+8p, +8)
    const uint4* wsd0 = (const uint4*)(g_hWsd + r0 * 320) + p;         // + 8*m
    const uint4* wsd1 = (const uint4*)(g_hWsd + (r0 + 64) * 320) + p;  // + 8*m

    // ---- init state ----
    for (int i = tid; i < LPREV; i += NTH) ring[i] = prev0[b * LPREV + i];
    if (tid < 3 * S) {
        st[0][tid >> 6][tid & 63] = 0.f;
        sth[0][tid >> 6][tid & 63] = __half(0.f);
    }
    if (tid >= 132 && tid < 160) subin[tid] = 0.f;
    if (tid < 64) {   // initial psub seeding (stage L does it for later subframes)
        float v = prev0[b * LPREV + 448 + tid];
        subin[tid] = v;
        __half hv = __float2half(v);
        skiph[256 + tid] = hv;
        xcath[64 + tid] = hv;
    }
    int head = 0;
    int pb = 0;
    __syncthreads();

    const __half2 hz = __floats2half2_rn(0.f, 0.f);

    for (int tf = 0; tf < NFRAMES; tf++) {
        const int bt = b * NFRAMES + tf;
        // ---- frame top: stage fwpre for all 4 subframes + period ----
        if (tid < 256) fwp4[tid] = __ldg(&g_fwpre[(long)bt * 256 + tid]);
        if (tid == 0) period_sh = __ldg(&g_period[bt]);
        __syncthreads();
        const int period = period_sh;

        for (int k = 0; k < 4; k++) {
            float sd0 = 0.f, sd1 = 0.f;   // incremental Wsd @ skip accumulators

            // ---- A: lookback only (psub seeded by previous L / init) ----
            if (tid >= 64 && tid < 132) {
                int i = tid - 64;
                int idx = LPREV - period + i - 2;
                if (idx >= LPREV) idx -= period;
                subin[tid] = ring[(head + idx) & 511];
            }
            __syncthreads();

            // ---- B: fwraw = tanh(Wfw2 @ subin + fwpre)  [+ Wsd psub part]
            float fwreg;
            {
                uint4 w0 = __ldg(wsd0 + 32), w1 = __ldg(wsd1 + 32);   // part m=4 (psub)
                const float4* xs4 = (const float4*)subin;
                float a = 0.f;
                #pragma unroll
                for (int j = 0; j < 5; j++) {
                    float4 w = rfw2v[j];
                    float4 x = xs4[p + 8 * j];
                    a = fmaf(w.x, x.x, a); a = fmaf(w.y, x.y, a);
                    a = fmaf(w.z, x.z, a); a = fmaf(w.w, x.w, a);
                }
                fwreg = tanh_f(red8(a) + fwp4[k * 64 + r0]);
                if (p == 0) fwv[r0] = fwreg;
                uint4 xs = ((const uint4*)(skiph + 256))[p];
                sd0 += hsum2f(dot8hh(w0, xs, hz));
                sd1 += hsum2f(dot8hh(w1, xs, hz));
            }
            __syncthreads();

            // ---- C: fw = fwraw * sigm(Wfwg @ fwv)   (fp32 register gate)
            {
                const float4* x = (const float4*)fwv;
                float acc = red8(dot8f(rgf[3][0], rgf[3][1], x[2 * p], x[2 * p + 1]));
                fwreg = fwreg * sigm(acc);
                if (p == 0) {
                    __half hv = __float2half(fwreg);
                    skiph[192 + r0] = hv;
                    xcath[r0] = hv;
                }
            }
            __syncthreads();

            // ---- 3 x (GRU fused + GLU fused), half2 HFMA2 dots ----
            #pragma unroll
            for (int L = 0; L < 3; L++) {
                const __half* WI = sWih + L * 192 * 128;
                const __half* WH = sWhh + L * 192 * 64;
                const float* sto = st[pb][L];
                float* stn = st[pb ^ 1][L];
                __half* stnh = sth[pb ^ 1][L];
                float streg;
                {
                    // Wsd part for this stage: L=0 -> fw (m=3), L=1 -> o1 (m=0), L=2 -> o2 (m=1)
                    const int m = (L == 0) ? 3 : (L - 1);
                    uint4 w0 = __ldg(wsd0 + 8 * m), w1 = __ldg(wsd1 + 8 * m);

                    const uint4* xh = (const uint4*)xcath;
                    uint4 xa = xh[p], xb = xh[p + 8];
                    uint4 sv = ((const uint4*)sth[pb][L])[p];
                    float gi[3], gh[3];
                    #pragma unroll
                    for (int it = 0; it < 3; it++) {
                        const uint4* wi = (const uint4*)(WI + (r0 + (it << 6)) * 128);
                        __half2 acc = dot8hh(wi[p], xa, hz);
                        acc = dot8hh(wi[p + 8], xb, acc);
                        gi[it] = red8(hsum2f(acc));
                        const uint4* wh = (const uint4*)(WH + (r0 + (it << 6)) * 64);
                        gh[it] = red8(hsum2f(dot8hh(wh[p], sv, hz)));
                    }
                    float r = sigm(gi[0] + gh[0]);
                    float z = sigm(gi[1] + gh[1]);
                    float n = tanh_f(gi[2] + r * gh[2]);
                    streg = (1.f - z) * n + z * sto[r0];
                    if (p == 0) {
                        stn[r0] = streg;
                        stnh[r0] = __float2half(streg);
                    }

                    uint4 xm = ((const uint4*)(skiph + 64 * m))[p];
                    sd0 += hsum2f(dot8hh(w0, xm, hz));
                    sd1 += hsum2f(dot8hh(w1, xm, hz));
                }
                __syncthreads();
                {
                    const float4* x = (const float4*)stn;
                    float acc = red8(dot8f(rgf[L][0], rgf[L][1], x[2 * p], x[2 * p + 1]));
                    float v = streg * sigm(acc);
                    if (p == 0) {
                        __half hv = __float2half(v);
                        skiph[64 * L + r0] = hv;
                        if (L < 2) xcath[r0] = hv;
                    }
                }
                __syncthreads();
            }

            // ---- J (mini): add o3 part, finalize sdv ----
            float sdva[2];
            {
                uint4 w0 = __ldg(wsd0 + 16), w1 = __ldg(wsd1 + 16);   // part m=2 (o3)
                uint4 xm = ((const uint4*)(skiph + 128))[p];
                sd0 += hsum2f(dot8hh(w0, xm, hz));
                sd1 += hsum2f(dot8hh(w1, xm, hz));
                sdva[0] = tanh_f(red8(sd0));
                sdva[1] = tanh_f(red8(sd1));
                if (p == 0) {
                    sdvh[r0] = __float2half(sdva[0]);
                    sdvh[64 + r0] = __float2half(sdva[1]);
                }
            }
            __syncthreads();

            // ---- K: sov = sdv * sigm(Wsg @ sdv)   (register fp16, half2 dots)
            {
                const uint4* xh = (const uint4*)sdvh;
                uint4 xa = xh[p], xb = xh[p + 8];
                #pragma unroll
                for (int it = 0; it < 2; it++) {
                    __half2 acc = dot8hh(rsgh[it][0], xa, hz);
                    acc = dot8hh(rsgh[it][1], xb, acc);
                    float a = red8(hsum2f(acc));
                    if (p == 0) sovh[r0 + 64 * it] = __float2half(sdva[it] * sigm(a));
                }
            }
            __syncthreads();

            // ---- L: out = tanh(Wout @ sov); emit + ring update + psub seed ----
            {
                const uint4* xh = (const uint4*)sovh;
                __half2 acc = dot8hh(routh[0], xh[p], hz);
                acc = dot8hh(routh[1], xh[p + 8], acc);
                float out = tanh_f(red8(hsum2f(acc)));
                if (p == 0) {
                    outp[(long)b * (NFRAMES * 4 * S) + tf * (4 * S) + k * S + r0] = out;
                    ring[(head + r0) & 511] = out;
                    // seed next subframe's psub (out == next prev_sub)
                    subin[r0] = out;
                    __half hv = __float2half(out);
                    skiph[256 + r0] = hv;
                    xcath[64 + r0] = hv;
                }
            }
            head = (head + 64) & 511;
            pb ^= 1;
            __syncthreads();
        }
    }
}

extern "C" void kernel_launch(void* const* d_in, const int* in_sizes, int n_in,
                              void* d_out, int out_size)
{
    const float* feats = (const float*)d_in[0];
    const float* glob  = (const float*)d_in[1];
    const float* prev0 = (const float*)d_in[2];
    const float* Wc1   = (const float*)d_in[3];
    const float* Wc2   = (const float*)d_in[4];
    const float* Wc3   = (const float*)d_in[5];
    const float* Wfw   = (const float*)d_in[6];
    const float* Wfw_g = (const float*)d_in[7];
    const float* Wih1  = (const float*)d_in[8];
    const float* Whh1  = (const float*)d_in[9];
    const float* Wih2  = (const float*)d_in[10];
    const float* Whh2  = (const float*)d_in[11];
    const float* Wih3  = (const float*)d_in[12];
    const float* Whh3  = (const float*)d_in[13];
    const float* Wg1   = (const float*)d_in[14];
    const float* Wg2   = (const float*)d_in[15];
    const float* Wg3   = (const float*)d_in[16];
    const float* Wsg   = (const float*)d_in[17];
    const float* Wsd   = (const float*)d_in[18];
    const float* Wout  = (const float*)d_in[19];
    float* outp = (float*)d_out;

    static bool attr_set = false;
    if (!attr_set) {
        cudaFuncSetAttribute(fargan_kernel,
                             cudaFuncAttributeMaxDynamicSharedMemorySize, DYN_BYTES);
        attr_set = true;
    }

    build_x_kernel<<<NBT, 64>>>(feats, glob, Wsd);
    gemm_tanh_kernel<<<dim3(4, 100), 256>>>(Wc1, 0, 256, 256);
    gemm_tanh_kernel<<<dim3(4, 100), 256>>>(Wc2, 1, 256, 256);
    gemm_tanh_kernel<<<dim3(8, 100), 256>>>(Wc3, 2, 512, 256);
    fwpre_kernel<<<NBT, 256>>>(Wfw);
    fargan_kernel<<<BATCH, NTH, DYN_BYTES>>>(prev0,
                                  Wfw, Wfw_g,
                                  Wih1, Whh1, Wih2, Whh2, Wih3, Whh3,
                                  Wg1, Wg2, Wg3, Wsg, Wout, outp);
}